// round 2
// baseline (speedup 1.0000x reference)
#include <cuda_runtime.h>
#include <cuda_bf16.h>
#include <math.h>

// Problem constants
#define BB    8
#define SS    512
#define DD    1024
#define NBLK  8
#define KSEL  4
#define MM    (BB*SS)          // 4096
#define BSD   (BB*SS*DD)       // 4,194,304

// ---------------- scratch (no cudaMalloc allowed) ----------------
__device__ float g_tmpA[BSD];          // LN outputs (M x D)
__device__ float g_tmpB[BSD*2];        // FF intermediate (M x 2D max)
__device__ float g_cmean[BB*DD];       // mean over S of cortical input (B,D)
__device__ float g_bmean[BB*DD];       // mean over S of brainstem input (B,D)
__device__ float g_gate_c[NBLK*DD];
__device__ float g_te_c[NBLK*DD];
__device__ float g_gate_b[NBLK*DD];
__device__ float g_te_b[NBLK*DD];
__device__ int   g_ctop[KSEL];
__device__ int   g_btop[KSEL];

// ---------------- mean over seq dim: (B,S,D) -> (B,D) ----------------
__global__ void mean_kernel(const float* __restrict__ x, float* __restrict__ out) {
    int idx = blockIdx.x * blockDim.x + threadIdx.x;   // over B*D
    if (idx >= BB * DD) return;
    int b = idx / DD;
    int d = idx - b * DD;
    const float* p = x + (size_t)b * SS * DD + d;
    float s = 0.f;
#pragma unroll 8
    for (int i = 0; i < SS; ++i) s += p[(size_t)i * DD];
    out[idx] = s * (1.f / SS);
}

// ---------------- gate/te precompute for all NB blocks ----------------
__global__ void prep_kernel(const float* __restrict__ c_tg,
                            const float* __restrict__ b_tg,
                            const float* __restrict__ tor) {
    int i = blockIdx.x * blockDim.x + threadIdx.x;
    if (i >= NBLK * DD) return;
    float t = tor[i & (DD - 1)];
    float gc = 1.f / (1.f + expf(-c_tg[i]));
    g_gate_c[i] = gc;
    g_te_c[i]   = gc * t;
    float gb = 1.f / (1.f + expf(-b_tg[i]));
    g_gate_b[i] = gb;
    g_te_b[i]   = gb * t;
}

// ---------------- routing: sigmoid selector on batch-0 mean, top-4 ----------------
__global__ void routing_kernel(const float* __restrict__ csw, const float* __restrict__ csb,
                               const float* __restrict__ bsw, const float* __restrict__ bsb) {
    __shared__ float red[256];
    __shared__ float score[NBLK];
    int tid = threadIdx.x;
    for (int p = 0; p < 2; ++p) {
        const float* mean = p ? g_bmean : g_cmean;   // batch-0 row = first DD
        const float* sw   = p ? bsw : csw;
        const float* sb   = p ? bsb : csb;
        int* top          = p ? g_btop : g_ctop;
        float a[NBLK];
#pragma unroll
        for (int j = 0; j < NBLK; ++j) a[j] = 0.f;
        for (int d = tid; d < DD; d += 256) {
            float m = mean[d];
#pragma unroll
            for (int j = 0; j < NBLK; ++j) a[j] += m * sw[d * NBLK + j];
        }
        for (int j = 0; j < NBLK; ++j) {
            red[tid] = a[j];
            __syncthreads();
            for (int o = 128; o > 0; o >>= 1) {
                if (tid < o) red[tid] += red[tid + o];
                __syncthreads();
            }
            if (tid == 0) score[j] = red[0] + sb[j];
            __syncthreads();
        }
        if (tid == 0) {
            float adj[NBLK];
            bool used[NBLK];
            for (int j = 0; j < NBLK; ++j) {
                adj[j] = (1.f / (1.f + expf(-score[j]))) * 0.6f + 0.5f * 0.4f;
                used[j] = false;
            }
            for (int k = 0; k < KSEL; ++k) {   // descending, ties -> lower index (matches lax.top_k)
                int best = -1; float bv = -1e30f;
                for (int j = 0; j < NBLK; ++j)
                    if (!used[j] && adj[j] > bv) { bv = adj[j]; best = j; }
                used[best] = true;
                top[k] = best;
            }
        }
        __syncthreads();
    }
}

// ---------------- LayerNorm over last dim (one block per row) ----------------
__global__ void ln_kernel(const float* __restrict__ x, const float* __restrict__ g0,
                          const float* __restrict__ b0, float* __restrict__ y,
                          const int* __restrict__ top, int step) {
    int row = blockIdx.x;
    int tid = threadIdx.x;
    int blk = top[step];
    float4 v = ((const float4*)(x + (size_t)row * DD))[tid];   // 256 thr * 4 = 1024
    float s = v.x + v.y + v.z + v.w;
    float q = v.x * v.x + v.y * v.y + v.z * v.z + v.w * v.w;
#pragma unroll
    for (int o = 16; o > 0; o >>= 1) {
        s += __shfl_down_sync(0xffffffffu, s, o);
        q += __shfl_down_sync(0xffffffffu, q, o);
    }
    __shared__ float ssum[8], sq[8];
    __shared__ float s_mu, s_r;
    int w = tid >> 5, l = tid & 31;
    if (l == 0) { ssum[w] = s; sq[w] = q; }
    __syncthreads();
    if (tid == 0) {
        float S = 0.f, Q = 0.f;
#pragma unroll
        for (int i = 0; i < 8; ++i) { S += ssum[i]; Q += sq[i]; }
        float mu  = S * (1.f / DD);
        float var = Q * (1.f / DD) - mu * mu;
        s_mu = mu;
        s_r  = rsqrtf(var + 1e-5f);
    }
    __syncthreads();
    float mu = s_mu, r = s_r;
    float4 gg = ((const float4*)(g0 + (size_t)blk * DD))[tid];
    float4 bb = ((const float4*)(b0 + (size_t)blk * DD))[tid];
    float4 o;
    o.x = (v.x - mu) * r * gg.x + bb.x;
    o.y = (v.y - mu) * r * gg.y + bb.y;
    o.z = (v.z - mu) * r * gg.z + bb.z;
    o.w = (v.w - mu) * r * gg.w + bb.w;
    ((float4*)(y + (size_t)row * DD))[tid] = o;
}

// ---------------- generic fp32 GEMM 128x128x16, fused epilogues ----------------
// C[M,N] = A[M,K] @ W[blk][K,N] (+ bias[blk][N]) with mode epilogue.
// mode 0: plain (+= C if addC)          mode 1: attn: *(1+te), resid + 0.5*v
// mode 2: exact GELU                    mode 3: tanh
// mode 4: + sig[b]*0.3*gate, resid + 0.5*v
__global__ __launch_bounds__(256, 2)
void gemm_kernel(const float* __restrict__ A, const float* __restrict__ W0,
                 const float* __restrict__ bias0, float* __restrict__ C,
                 int N, int Kd, int mode,
                 const int* __restrict__ top, int step,
                 const float* __restrict__ te0, const float* __restrict__ gate0,
                 const float* __restrict__ sig, const float* __restrict__ resid,
                 int addC) {
    __shared__ float As[2][16][132];
    __shared__ float Ws[2][16][132];
    int tid = threadIdx.x;
    int blk = (top != nullptr) ? top[step] : 0;
    const float* W    = W0 + (size_t)blk * Kd * N;
    const float* bias = bias0 ? (bias0 + (size_t)blk * N) : nullptr;
    int bm = blockIdx.y * 128, bn = blockIdx.x * 128;

    int arow = tid >> 2, acol = (tid & 3) << 2;       // A: 128 rows x 16 cols
    int wrow = tid >> 5, wcol = (tid & 31) << 2;      // W: 16 rows x 128 cols
    const float* A0 = A + (size_t)(bm + arow) * Kd + acol;
    const float* A1 = A0 + (size_t)64 * Kd;
    const float* Wb0 = W + (size_t)wrow * N + bn + wcol;
    const float* Wb1 = Wb0 + (size_t)8 * N;

    float4 pa0 = *(const float4*)A0;
    float4 pa1 = *(const float4*)A1;
    float4 pw0 = *(const float4*)Wb0;
    float4 pw1 = *(const float4*)Wb1;

    As[0][acol + 0][arow] = pa0.x; As[0][acol + 1][arow] = pa0.y;
    As[0][acol + 2][arow] = pa0.z; As[0][acol + 3][arow] = pa0.w;
    As[0][acol + 0][arow + 64] = pa1.x; As[0][acol + 1][arow + 64] = pa1.y;
    As[0][acol + 2][arow + 64] = pa1.z; As[0][acol + 3][arow + 64] = pa1.w;
    *(float4*)&Ws[0][wrow][wcol]     = pw0;
    *(float4*)&Ws[0][wrow + 8][wcol] = pw1;
    __syncthreads();

    int ty = tid >> 4, tx = tid & 15;
    float acc[8][8];
#pragma unroll
    for (int i = 0; i < 8; ++i)
#pragma unroll
        for (int j = 0; j < 8; ++j) acc[i][j] = 0.f;

    int nt = Kd >> 4;
    for (int t = 0; t < nt; ++t) {
        int cur = t & 1;
        if (t + 1 < nt) {
            pa0 = *(const float4*)(A0 + (t + 1) * 16);
            pa1 = *(const float4*)(A1 + (t + 1) * 16);
            pw0 = *(const float4*)(Wb0 + (size_t)(t + 1) * 16 * N);
            pw1 = *(const float4*)(Wb1 + (size_t)(t + 1) * 16 * N);
        }
#pragma unroll
        for (int kk = 0; kk < 16; ++kk) {
            float a[8], w[8];
            *(float4*)&a[0] = *(const float4*)&As[cur][kk][ty * 8];
            *(float4*)&a[4] = *(const float4*)&As[cur][kk][ty * 8 + 4];
            *(float4*)&w[0] = *(const float4*)&Ws[cur][kk][tx * 8];
            *(float4*)&w[4] = *(const float4*)&Ws[cur][kk][tx * 8 + 4];
#pragma unroll
            for (int i = 0; i < 8; ++i)
#pragma unroll
                for (int j = 0; j < 8; ++j) acc[i][j] += a[i] * w[j];
        }
        if (t + 1 < nt) {
            int nx = (t + 1) & 1;
            As[nx][acol + 0][arow] = pa0.x; As[nx][acol + 1][arow] = pa0.y;
            As[nx][acol + 2][arow] = pa0.z; As[nx][acol + 3][arow] = pa0.w;
            As[nx][acol + 0][arow + 64] = pa1.x; As[nx][acol + 1][arow + 64] = pa1.y;
            As[nx][acol + 2][arow + 64] = pa1.z; As[nx][acol + 3][arow + 64] = pa1.w;
            *(float4*)&Ws[nx][wrow][wcol]     = pw0;
            *(float4*)&Ws[nx][wrow + 8][wcol] = pw1;
        }
        __syncthreads();
    }

    int rbase = bm + ty * 8;
    int cbase = bn + tx * 8;
#pragma unroll
    for (int i = 0; i < 8; ++i) {
        int r = rbase + i;
        size_t off = (size_t)r * N;
        int bidx = r >> 9;   // / S (=512)
#pragma unroll
        for (int j = 0; j < 8; ++j) {
            int c = cbase + j;
            float v = acc[i][j];
            if (bias) v += bias[c];
            if (mode == 1) {
                v *= (1.f + te0[(size_t)blk * DD + c]);
                v = resid[off + c] + 0.5f * v;
            } else if (mode == 2) {
                v = 0.5f * v * (1.f + erff(v * 0.70710678118654752f));
            } else if (mode == 3) {
                v = tanhf(v);
            } else if (mode == 4) {
                v += sig[(size_t)bidx * DD + c] * 0.3f * gate0[(size_t)blk * DD + c];
                v = resid[off + c] + 0.5f * v;
            } else {
                if (addC) v += C[off + c];
            }
            C[off + c] = v;
        }
    }
}

// ---------------- host orchestration ----------------
extern "C" void kernel_launch(void* const* d_in, const int* in_sizes, int n_in,
                              void* d_out, int out_size) {
    const float* ci     = (const float*)d_in[0];
    const float* bi     = (const float*)d_in[1];
    const float* tor    = (const float*)d_in[2];
    const float* cln1g  = (const float*)d_in[3];
    const float* cln1b  = (const float*)d_in[4];
    const float* cattw  = (const float*)d_in[5];
    const float* cattb  = (const float*)d_in[6];
    const float* cln2g  = (const float*)d_in[7];
    const float* cln2b  = (const float*)d_in[8];
    const float* cff1w  = (const float*)d_in[9];
    const float* cff1b  = (const float*)d_in[10];
    const float* cff2w  = (const float*)d_in[11];
    const float* cff2b  = (const float*)d_in[12];
    const float* ctg    = (const float*)d_in[13];
    const float* bln1g  = (const float*)d_in[14];
    const float* bln1b  = (const float*)d_in[15];
    const float* battw  = (const float*)d_in[16];
    const float* battb  = (const float*)d_in[17];
    const float* bln2g  = (const float*)d_in[18];
    const float* bln2b  = (const float*)d_in[19];
    const float* bff1w  = (const float*)d_in[20];
    const float* bff1b  = (const float*)d_in[21];
    const float* bff2w  = (const float*)d_in[22];
    const float* bff2b  = (const float*)d_in[23];
    const float* btg    = (const float*)d_in[24];
    const float* cselw  = (const float*)d_in[25];
    const float* cselb  = (const float*)d_in[26];
    const float* bselw  = (const float*)d_in[27];
    const float* bselb  = (const float*)d_in[28];
    const float* crossw = (const float*)d_in[29];
    const float* crossb = (const float*)d_in[30];

    float* outC = (float*)d_out;            // cortical_h
    float* outB = outC + (size_t)BSD;       // brainstem_h
    float* outF = outC + (size_t)2 * BSD;   // fused

    float *tmpA, *tmpB, *cmean, *bmean, *gc, *tec, *gb, *teb;
    int *ctop, *btop;
    cudaGetSymbolAddress((void**)&tmpA,  g_tmpA);
    cudaGetSymbolAddress((void**)&tmpB,  g_tmpB);
    cudaGetSymbolAddress((void**)&cmean, g_cmean);
    cudaGetSymbolAddress((void**)&bmean, g_bmean);
    cudaGetSymbolAddress((void**)&gc,    g_gate_c);
    cudaGetSymbolAddress((void**)&tec,   g_te_c);
    cudaGetSymbolAddress((void**)&gb,    g_gate_b);
    cudaGetSymbolAddress((void**)&teb,   g_te_b);
    cudaGetSymbolAddress((void**)&ctop,  g_ctop);
    cudaGetSymbolAddress((void**)&btop,  g_btop);

    // state init: pathway states live in d_out and are updated in place
    cudaMemcpyAsync(outC, ci, (size_t)BSD * sizeof(float), cudaMemcpyDeviceToDevice);
    cudaMemcpyAsync(outB, bi, (size_t)BSD * sizeof(float), cudaMemcpyDeviceToDevice);

    mean_kernel<<<(BB * DD + 255) / 256, 256>>>(ci, cmean);
    mean_kernel<<<(BB * DD + 255) / 256, 256>>>(bi, bmean);
    routing_kernel<<<1, 256>>>(cselw, cselb, bselw, bselb);
    prep_kernel<<<(NBLK * DD + 255) / 256, 256>>>(ctg, btg, tor);

    dim3 g8(8, 32), g16(16, 32);
    for (int s = 0; s < KSEL; ++s) {
        // cortical block
        ln_kernel<<<MM, 256>>>(outC, cln1g, cln1b, tmpA, ctop, s);
        gemm_kernel<<<g8, 256>>>(tmpA, cattw, cattb, outC, 1024, 1024, 1,
                                 ctop, s, tec, nullptr, nullptr, outC, 0);
        ln_kernel<<<MM, 256>>>(outC, cln2g, cln2b, tmpA, ctop, s);
        gemm_kernel<<<g16, 256>>>(tmpA, cff1w, cff1b, tmpB, 2048, 1024, 2,
                                  ctop, s, nullptr, nullptr, nullptr, nullptr, 0);
        gemm_kernel<<<g8, 256>>>(tmpB, cff2w, cff2b, outC, 1024, 2048, 4,
                                 ctop, s, nullptr, gc, bmean, outC, 0);
        // brainstem block
        ln_kernel<<<MM, 256>>>(outB, bln1g, bln1b, tmpA, btop, s);
        gemm_kernel<<<g8, 256>>>(tmpA, battw, battb, outB, 1024, 1024, 1,
                                 btop, s, teb, nullptr, nullptr, outB, 0);
        ln_kernel<<<MM, 256>>>(outB, bln2g, bln2b, tmpA, btop, s);
        gemm_kernel<<<g8, 256>>>(tmpA, bff1w, bff1b, tmpB, 1024, 1024, 3,
                                 btop, s, nullptr, nullptr, nullptr, nullptr, 0);
        gemm_kernel<<<g8, 256>>>(tmpB, bff2w, bff2b, outB, 1024, 1024, 4,
                                 btop, s, nullptr, gb, cmean, outB, 0);
    }

    // cross projection: fused = outC @ W[0:D] + outB @ W[D:2D] + b
    gemm_kernel<<<g8, 256>>>(outC, crossw, nullptr, outF, 1024, 1024, 0,
                             nullptr, 0, nullptr, nullptr, nullptr, nullptr, 0);
    gemm_kernel<<<g8, 256>>>(outB, crossw + (size_t)DD * DD, crossb, outF, 1024, 1024, 0,
                             nullptr, 0, nullptr, nullptr, nullptr, nullptr, 1);
}

// round 9
// speedup vs baseline: 1.6231x; 1.6231x over previous
#include <cuda_runtime.h>
#include <cuda_bf16.h>
#include <math.h>
#include <stdint.h>

// Problem constants
#define BB    8
#define SS    512
#define DD    1024
#define NBLK  8
#define KSEL  4
#define MM    (BB*SS)          // 4096
#define BSD   (BB*SS*DD)       // 4,194,304

// GEMM tiling: CTA 128x128, K-chunk 64, 8 warps (2Mx4N), warp tile 64x32
#define STAGE 65536            // Ahi 16K + Alo 16K + Bhi 16K + Blo 16K
#define GEMM_SMEM (2*STAGE)    // 131072

// Weight regions (elements) in transposed split-bf16 buffers
#define OFF_CATTN 0ull
#define OFF_CFF1  8388608ull
#define OFF_CFF2  25165824ull
#define OFF_BATTN 41943040ull
#define OFF_BFF1  50331648ull
#define OFF_BFF2  58720256ull
#define OFF_CROSS 67108864ull
#define WTOT      69206016ull

// ---------------- scratch (no cudaMalloc allowed) ----------------
__device__ float g_tmpA[BSD];          // LN outputs (M x D)
__device__ float g_tmpB[BSD*2];        // FF intermediate (M x 2D max)
__device__ float g_cmean[BB*DD];
__device__ float g_bmean[BB*DD];
__device__ float g_gate_c[NBLK*DD];
__device__ float g_te_c[NBLK*DD];
__device__ float g_gate_b[NBLK*DD];
__device__ float g_te_b[NBLK*DD];
__device__ int   g_ctop[KSEL];
__device__ int   g_btop[KSEL];
__device__ __nv_bfloat16 g_whi[WTOT];  // transposed weights, hi part [N,K]
__device__ __nv_bfloat16 g_wlo[WTOT];  // lo part

// ---------------- helpers ----------------
__device__ __forceinline__ uint32_t smem_u32(const void* p) {
    uint32_t a;
    asm("{ .reg .u64 t; cvta.to.shared.u64 t, %1; cvt.u32.u64 %0, t; }" : "=r"(a) : "l"(p));
    return a;
}
__device__ __forceinline__ void cp16(uint32_t saddr, const void* g) {
    asm volatile("cp.async.cg.shared.global [%0], [%1], 16;" :: "r"(saddr), "l"(g));
}
__device__ __forceinline__ void cp_commit() { asm volatile("cp.async.commit_group;" ::: "memory"); }
__device__ __forceinline__ void cp_wait0()  { asm volatile("cp.async.wait_group 0;" ::: "memory"); }

__device__ __forceinline__ void ldm_x4(uint32_t* r, uint32_t addr) {
    asm volatile("ldmatrix.sync.aligned.m8n8.x4.shared.b16 {%0,%1,%2,%3}, [%4];"
        : "=r"(r[0]), "=r"(r[1]), "=r"(r[2]), "=r"(r[3]) : "r"(addr));
}
__device__ __forceinline__ void mma_bf16(float* c, const uint32_t* a, uint32_t b0, uint32_t b1) {
    asm volatile("mma.sync.aligned.m16n8k16.row.col.f32.bf16.bf16.f32 "
        "{%0,%1,%2,%3}, {%4,%5,%6,%7}, {%8,%9}, {%0,%1,%2,%3};"
        : "+f"(c[0]), "+f"(c[1]), "+f"(c[2]), "+f"(c[3])
        : "r"(a[0]), "r"(a[1]), "r"(a[2]), "r"(a[3]), "r"(b0), "r"(b1));
}
__device__ __forceinline__ uint32_t pack_hi(float a, float b, uint32_t& lo_out) {
    __nv_bfloat16 ha = __float2bfloat16(a);
    __nv_bfloat16 hb = __float2bfloat16(b);
    float la = a - __bfloat162float(ha);
    float lb = b - __bfloat162float(hb);
    __nv_bfloat162 h; h.x = ha; h.y = hb;
    __nv_bfloat162 l; l.x = __float2bfloat16(la); l.y = __float2bfloat16(lb);
    lo_out = *(uint32_t*)&l;
    return *(uint32_t*)&h;
}

// ---------------- mean over seq dim ----------------
__global__ void mean_kernel(const float* __restrict__ x, float* __restrict__ out) {
    int idx = blockIdx.x * blockDim.x + threadIdx.x;
    if (idx >= BB * DD) return;
    int b = idx / DD, d = idx - b * DD;
    const float* p = x + (size_t)b * SS * DD + d;
    float s = 0.f;
#pragma unroll 8
    for (int i = 0; i < SS; ++i) s += p[(size_t)i * DD];
    out[idx] = s * (1.f / SS);
}

// ---------------- gate/te precompute ----------------
__global__ void prep_kernel(const float* __restrict__ c_tg, const float* __restrict__ b_tg,
                            const float* __restrict__ tor) {
    int i = blockIdx.x * blockDim.x + threadIdx.x;
    if (i >= NBLK * DD) return;
    float t = tor[i & (DD - 1)];
    float gc = 1.f / (1.f + expf(-c_tg[i]));
    g_gate_c[i] = gc; g_te_c[i] = gc * t;
    float gb = 1.f / (1.f + expf(-b_tg[i]));
    g_gate_b[i] = gb; g_te_b[i] = gb * t;
}

// ---------------- routing ----------------
__global__ void routing_kernel(const float* __restrict__ csw, const float* __restrict__ csb,
                               const float* __restrict__ bsw, const float* __restrict__ bsb) {
    __shared__ float red[256];
    __shared__ float score[NBLK];
    int tid = threadIdx.x;
    for (int p = 0; p < 2; ++p) {
        const float* mean = p ? g_bmean : g_cmean;
        const float* sw   = p ? bsw : csw;
        const float* sb   = p ? bsb : csb;
        int* top          = p ? g_btop : g_ctop;
        float a[NBLK];
#pragma unroll
        for (int j = 0; j < NBLK; ++j) a[j] = 0.f;
        for (int d = tid; d < DD; d += 256) {
            float m = mean[d];
#pragma unroll
            for (int j = 0; j < NBLK; ++j) a[j] += m * sw[d * NBLK + j];
        }
        for (int j = 0; j < NBLK; ++j) {
            red[tid] = a[j];
            __syncthreads();
            for (int o = 128; o > 0; o >>= 1) {
                if (tid < o) red[tid] += red[tid + o];
                __syncthreads();
            }
            if (tid == 0) score[j] = red[0] + sb[j];
            __syncthreads();
        }
        if (tid == 0) {
            float adj[NBLK]; bool used[NBLK];
            for (int j = 0; j < NBLK; ++j) {
                adj[j] = (1.f / (1.f + expf(-score[j]))) * 0.6f + 0.2f;
                used[j] = false;
            }
            for (int k = 0; k < KSEL; ++k) {
                int best = 0; float bv = -1e30f;
                for (int j = 0; j < NBLK; ++j)
                    if (!used[j] && adj[j] > bv) { bv = adj[j]; best = j; }
                used[best] = true;
                top[k] = best;
            }
        }
        __syncthreads();
    }
}

// ---------------- LayerNorm ----------------
__global__ void ln_kernel(const float* __restrict__ x, const float* __restrict__ g0,
                          const float* __restrict__ b0, float* __restrict__ y,
                          const int* __restrict__ top, int step) {
    int row = blockIdx.x, tid = threadIdx.x;
    int blk = top[step];
    float4 v = ((const float4*)(x + (size_t)row * DD))[tid];
    float s = v.x + v.y + v.z + v.w;
    float q = v.x * v.x + v.y * v.y + v.z * v.z + v.w * v.w;
#pragma unroll
    for (int o = 16; o > 0; o >>= 1) {
        s += __shfl_down_sync(0xffffffffu, s, o);
        q += __shfl_down_sync(0xffffffffu, q, o);
    }
    __shared__ float ssum[8], sq[8];
    __shared__ float s_mu, s_r;
    int w = tid >> 5, l = tid & 31;
    if (l == 0) { ssum[w] = s; sq[w] = q; }
    __syncthreads();
    if (tid == 0) {
        float S = 0.f, Q = 0.f;
#pragma unroll
        for (int i = 0; i < 8; ++i) { S += ssum[i]; Q += sq[i]; }
        float mu = S * (1.f / DD);
        float var = Q * (1.f / DD) - mu * mu;
        s_mu = mu; s_r = rsqrtf(var + 1e-5f);
    }
    __syncthreads();
    float mu = s_mu, r = s_r;
    float4 gg = ((const float4*)(g0 + (size_t)blk * DD))[tid];
    float4 bb = ((const float4*)(b0 + (size_t)blk * DD))[tid];
    float4 o;
    o.x = (v.x - mu) * r * gg.x + bb.x;
    o.y = (v.y - mu) * r * gg.y + bb.y;
    o.z = (v.z - mu) * r * gg.z + bb.z;
    o.w = (v.w - mu) * r * gg.w + bb.w;
    ((float4*)(y + (size_t)row * DD))[tid] = o;
}

// ---------------- transpose + split-bf16 convert: W[K,N] -> Wt[N,K] hi/lo ----------------
__global__ void transpose_kernel(const float* __restrict__ src,
                                 __nv_bfloat16* __restrict__ dsthi,
                                 __nv_bfloat16* __restrict__ dstlo,
                                 int Kd, int N) {
    __shared__ float ts[32][33];
    int z = blockIdx.z;
    src   += (size_t)z * Kd * N;
    dsthi += (size_t)z * Kd * N;
    dstlo += (size_t)z * Kd * N;
    int n0 = blockIdx.x * 32, k0 = blockIdx.y * 32;
    int t = threadIdx.x;
    {
        int kk = t >> 3, nn4 = (t & 7) * 4;
        float4 v = *(const float4*)(src + (size_t)(k0 + kk) * N + n0 + nn4);
        ts[kk][nn4 + 0] = v.x; ts[kk][nn4 + 1] = v.y;
        ts[kk][nn4 + 2] = v.z; ts[kk][nn4 + 3] = v.w;
    }
    __syncthreads();
    {
        int nn = t >> 3, kk4 = (t & 7) * 4;
        uint32_t h0, h1, l0, l1;
        h0 = pack_hi(ts[kk4 + 0][nn], ts[kk4 + 1][nn], l0);
        h1 = pack_hi(ts[kk4 + 2][nn], ts[kk4 + 3][nn], l1);
        size_t o = (size_t)(n0 + nn) * Kd + k0 + kk4;
        *(uint2*)(dsthi + o) = make_uint2(h0, h1);
        *(uint2*)(dstlo + o) = make_uint2(l0, l1);
    }
}

// ---------------- epilogue helper ----------------
__device__ __forceinline__ float epi_apply(float x, int mode, const float* bias, int c,
                                           const float* te, const float* gate,
                                           const float* sig, const float* resid,
                                           const float* Cp, int addC, size_t off, int bidx) {
    if (bias) x += bias[c];
    if (mode == 1) {
        x *= (1.f + te[c]);
        x = resid[off + c] + 0.5f * x;
    } else if (mode == 2) {
        x = 0.5f * x * (1.f + erff(x * 0.70710678118654752f));
    } else if (mode == 3) {
        x = tanhf(x);
    } else if (mode == 4) {
        x += sig[(size_t)bidx * DD + c] * 0.3f * gate[c];
        x = resid[off + c] + 0.5f * x;
    } else if (addC) {
        x += Cp[off + c];
    }
    return x;
}

// ---------------- split-bf16 GEMM via ldmatrix + mma.sync (HMMA) ----------------
// C[M,N] = A[M,K](fp32) @ Wt[blk][N,K](split bf16) + bias, fused epilogues.
// smem stage layout (SW128 swizzle, 128B rows): Ahi@0, Alo@16K, Bhi@32K, Blo@48K.
__global__ __launch_bounds__(256, 1)
void gemm_mma(const float* __restrict__ A,
              const __nv_bfloat16* __restrict__ Whi0, const __nv_bfloat16* __restrict__ Wlo0,
              const float* __restrict__ bias0, float* __restrict__ C,
              int N, int Kd, int mode,
              const int* __restrict__ top, int step,
              const float* __restrict__ te0, const float* __restrict__ gate0,
              const float* __restrict__ sig, const float* __restrict__ resid, int addC) {
    extern __shared__ __align__(1024) char smem[];
    const uint32_t sb32 = smem_u32(smem);
    const int tid = threadIdx.x, lane = tid & 31, wid = tid >> 5;
    const int bm = blockIdx.y * 128, bn = blockIdx.x * 128;
    const int wm = (wid & 1) * 64, wn = (wid >> 1) * 32;
    const int blk = top ? top[step] : 0;
    const __nv_bfloat16* Whi = Whi0 + (size_t)blk * N * Kd;
    const __nv_bfloat16* Wlo = Wlo0 + (size_t)blk * N * Kd;
    const float* bias = bias0 ? (bias0 + (size_t)blk * N) : nullptr;
    const float* te   = te0   ? (te0   + (size_t)blk * DD) : nullptr;
    const float* gate = gate0 ? (gate0 + (size_t)blk * DD) : nullptr;

    // loader mapping: 2 threads per row (128 rows), each covers half the 64-wide K-chunk
    const int lr = tid >> 1, lh = tid & 1;
    const float* Ap = A + (size_t)(bm + lr) * Kd + lh * 32;
    // NOTE: row base only — the (lh*4+i)*8 term below supplies the half-chunk offset.
    const __nv_bfloat16* Bhp = Whi + (size_t)(bn + lr) * Kd;
    const __nv_bfloat16* Blp = Wlo + (size_t)(bn + lr) * Kd;
    // swizzled smem offsets for this thread's stores
    uint32_t a_off[8], b_off[4];
#pragma unroll
    for (int i = 0; i < 8; ++i) {
        int kb = lh * 32 + i * 4;
        a_off[i] = (uint32_t)(lr * 128 + (((kb >> 3) ^ (lr & 7)) << 4) + (kb & 7) * 2);
    }
#pragma unroll
    for (int i = 0; i < 4; ++i) {
        int ch = lh * 4 + i;
        b_off[i] = (uint32_t)(lr * 128 + ((ch ^ (lr & 7)) << 4));
    }

    float acc[4][4][4];
#pragma unroll
    for (int mi = 0; mi < 4; ++mi)
#pragma unroll
        for (int ni = 0; ni < 4; ++ni)
#pragma unroll
            for (int q = 0; q < 4; ++q) acc[mi][ni][q] = 0.f;

    const int nt = Kd >> 6;
    float4 pa[8];

    // ---- prologue: stage 0 ----
    {
        uint32_t s0 = sb32;
#pragma unroll
        for (int i = 0; i < 4; ++i) {
            cp16(s0 + 32768 + b_off[i], Bhp + (lh * 4 + i) * 8);
            cp16(s0 + 49152 + b_off[i], Blp + (lh * 4 + i) * 8);
        }
        cp_commit();
#pragma unroll
        for (int i = 0; i < 8; ++i) pa[i] = *(const float4*)(Ap + i * 4);
#pragma unroll
        for (int i = 0; i < 8; ++i) {
            uint32_t l0, l1;
            uint32_t h0 = pack_hi(pa[i].x, pa[i].y, l0);
            uint32_t h1 = pack_hi(pa[i].z, pa[i].w, l1);
            *(uint2*)(smem + a_off[i])         = make_uint2(h0, h1);
            *(uint2*)(smem + 16384 + a_off[i]) = make_uint2(l0, l1);
        }
        cp_wait0();
    }
    __syncthreads();

    // ---- main loop ----
    for (int t = 0; t < nt; ++t) {
        const uint32_t buf = (uint32_t)(t & 1) * STAGE;
        const uint32_t nxt = (uint32_t)((t + 1) & 1) * STAGE;
        if (t + 1 < nt) {
            const int kb = (t + 1) << 6;
            // async B into next buffer (no regs)
#pragma unroll
            for (int i = 0; i < 4; ++i) {
                cp16(sb32 + nxt + 32768 + b_off[i], Bhp + kb + (lh * 4 + i) * 8);
                cp16(sb32 + nxt + 49152 + b_off[i], Blp + kb + (lh * 4 + i) * 8);
            }
            cp_commit();
            // A prefetch into regs
#pragma unroll
            for (int i = 0; i < 8; ++i) pa[i] = *(const float4*)(Ap + kb + i * 4);
        }
        // ---- MMA on current buffer ----
#pragma unroll
        for (int kk = 0; kk < 4; ++kk) {
            uint32_t ah[4][4], al[4][4], bh[2][4], bl[2][4];
#pragma unroll
            for (int mi = 0; mi < 4; ++mi) {
                int row = wm + mi * 16 + (lane & 15);
                int ch  = kk * 2 + (lane >> 4);
                uint32_t ad = sb32 + buf + (uint32_t)(row * 128 + ((ch ^ (row & 7)) << 4));
                ldm_x4(ah[mi], ad);
                ldm_x4(al[mi], ad + 16384);
            }
#pragma unroll
            for (int pr = 0; pr < 2; ++pr) {
                int mat = lane >> 3;
                int nrow = wn + pr * 16 + (mat >> 1) * 8 + (lane & 7);
                int ch = kk * 2 + (mat & 1);
                uint32_t bd = sb32 + buf + 32768 + (uint32_t)(nrow * 128 + ((ch ^ (nrow & 7)) << 4));
                ldm_x4(bh[pr], bd);
                ldm_x4(bl[pr], bd + 16384);
            }
#pragma unroll
            for (int mi = 0; mi < 4; ++mi)
#pragma unroll
                for (int ni = 0; ni < 4; ++ni) {
                    int pr = ni >> 1, o = (ni & 1) * 2;
                    mma_bf16(acc[mi][ni], ah[mi], bh[pr][o], bh[pr][o + 1]);
                    mma_bf16(acc[mi][ni], ah[mi], bl[pr][o], bl[pr][o + 1]);
                    mma_bf16(acc[mi][ni], al[mi], bh[pr][o], bh[pr][o + 1]);
                }
        }
        if (t + 1 < nt) {
            // convert+store A into next buffer, then drain B cp.async
#pragma unroll
            for (int i = 0; i < 8; ++i) {
                uint32_t l0, l1;
                uint32_t h0 = pack_hi(pa[i].x, pa[i].y, l0);
                uint32_t h1 = pack_hi(pa[i].z, pa[i].w, l1);
                *(uint2*)(smem + nxt + a_off[i])         = make_uint2(h0, h1);
                *(uint2*)(smem + nxt + 16384 + a_off[i]) = make_uint2(l0, l1);
            }
            cp_wait0();
        }
        __syncthreads();
    }

    // ---- epilogue: fragments -> global with fused modes ----
    const int g = lane >> 2, tg = lane & 3;
#pragma unroll
    for (int mi = 0; mi < 4; ++mi) {
        int r0 = bm + wm + mi * 16 + g;
#pragma unroll
        for (int ni = 0; ni < 4; ++ni) {
            int c = bn + wn + ni * 8 + tg * 2;
#pragma unroll
            for (int h = 0; h < 2; ++h) {
                int r = r0 + h * 8;
                size_t off = (size_t)r * N;
                int bidx = r >> 9;
                float x0 = epi_apply(acc[mi][ni][h * 2],     mode, bias, c,     te, gate, sig, resid, C, addC, off, bidx);
                float x1 = epi_apply(acc[mi][ni][h * 2 + 1], mode, bias, c + 1, te, gate, sig, resid, C, addC, off, bidx);
                *(float2*)&C[off + c] = make_float2(x0, x1);
            }
        }
    }
}

// ---------------- host orchestration ----------------
extern "C" void kernel_launch(void* const* d_in, const int* in_sizes, int n_in,
                              void* d_out, int out_size) {
    const float* ci     = (const float*)d_in[0];
    const float* bi     = (const float*)d_in[1];
    const float* tor    = (const float*)d_in[2];
    const float* cln1g  = (const float*)d_in[3];
    const float* cln1b  = (const float*)d_in[4];
    const float* cattw  = (const float*)d_in[5];
    const float* cattb  = (const float*)d_in[6];
    const float* cln2g  = (const float*)d_in[7];
    const float* cln2b  = (const float*)d_in[8];
    const float* cff1w  = (const float*)d_in[9];
    const float* cff1b  = (const float*)d_in[10];
    const float* cff2w  = (const float*)d_in[11];
    const float* cff2b  = (const float*)d_in[12];
    const float* ctg    = (const float*)d_in[13];
    const float* bln1g  = (const float*)d_in[14];
    const float* bln1b  = (const float*)d_in[15];
    const float* battw  = (const float*)d_in[16];
    const float* battb  = (const float*)d_in[17];
    const float* bln2g  = (const float*)d_in[18];
    const float* bln2b  = (const float*)d_in[19];
    const float* bff1w  = (const float*)d_in[20];
    const float* bff1b  = (const float*)d_in[21];
    const float* bff2w  = (const float*)d_in[22];
    const float* bff2b  = (const float*)d_in[23];
    const float* btg    = (const float*)d_in[24];
    const float* cselw  = (const float*)d_in[25];
    const float* cselb  = (const float*)d_in[26];
    const float* bselw  = (const float*)d_in[27];
    const float* bselb  = (const float*)d_in[28];
    const float* crossw = (const float*)d_in[29];
    const float* crossb = (const float*)d_in[30];

    float* outC = (float*)d_out;
    float* outB = outC + (size_t)BSD;
    float* outF = outC + (size_t)2 * BSD;

    float *tmpA, *tmpB;
    __nv_bfloat16 *whi, *wlo;
    int *ctop, *btop;
    cudaGetSymbolAddress((void**)&tmpA, g_tmpA);
    cudaGetSymbolAddress((void**)&tmpB, g_tmpB);
    cudaGetSymbolAddress((void**)&whi,  g_whi);
    cudaGetSymbolAddress((void**)&wlo,  g_wlo);
    cudaGetSymbolAddress((void**)&ctop, g_ctop);
    cudaGetSymbolAddress((void**)&btop, g_btop);
    float *cmean, *bmean, *gc, *tec, *gb, *teb;
    cudaGetSymbolAddress((void**)&cmean, g_cmean);
    cudaGetSymbolAddress((void**)&bmean, g_bmean);
    cudaGetSymbolAddress((void**)&gc,  g_gate_c);
    cudaGetSymbolAddress((void**)&tec, g_te_c);
    cudaGetSymbolAddress((void**)&gb,  g_gate_b);
    cudaGetSymbolAddress((void**)&teb, g_te_b);

    cudaFuncSetAttribute(gemm_mma, cudaFuncAttributeMaxDynamicSharedMemorySize, GEMM_SMEM);

    cudaMemcpyAsync(outC, ci, (size_t)BSD * sizeof(float), cudaMemcpyDeviceToDevice);
    cudaMemcpyAsync(outB, bi, (size_t)BSD * sizeof(float), cudaMemcpyDeviceToDevice);

    mean_kernel<<<(BB * DD + 255) / 256, 256>>>(ci, cmean);
    mean_kernel<<<(BB * DD + 255) / 256, 256>>>(bi, bmean);
    routing_kernel<<<1, 256>>>(cselw, cselb, bselw, bselb);
    prep_kernel<<<(NBLK * DD + 255) / 256, 256>>>(ctg, btg, tor);

    // weight pre-pass: transpose + split-bf16 convert
    transpose_kernel<<<dim3(32, 32, 8), 256>>>(cattw, whi + OFF_CATTN, wlo + OFF_CATTN, 1024, 1024);
    transpose_kernel<<<dim3(64, 32, 8), 256>>>(cff1w, whi + OFF_CFF1,  wlo + OFF_CFF1,  1024, 2048);
    transpose_kernel<<<dim3(32, 64, 8), 256>>>(cff2w, whi + OFF_CFF2,  wlo + OFF_CFF2,  2048, 1024);
    transpose_kernel<<<dim3(32, 32, 8), 256>>>(battw, whi + OFF_BATTN, wlo + OFF_BATTN, 1024, 1024);
    transpose_kernel<<<dim3(32, 32, 8), 256>>>(bff1w, whi + OFF_BFF1,  wlo + OFF_BFF1,  1024, 1024);
    transpose_kernel<<<dim3(32, 32, 8), 256>>>(bff2w, whi + OFF_BFF2,  wlo + OFF_BFF2,  1024, 1024);
    transpose_kernel<<<dim3(32, 32, 1), 256>>>(crossw, whi + OFF_CROSS, wlo + OFF_CROSS, 1024, 1024);
    transpose_kernel<<<dim3(32, 32, 1), 256>>>(crossw + (size_t)1024 * 1024,
                                               whi + OFF_CROSS + 1048576, wlo + OFF_CROSS + 1048576, 1024, 1024);

    dim3 g8(8, 32), g16(16, 32);
    for (int s = 0; s < KSEL; ++s) {
        // cortical
        ln_kernel<<<MM, 256>>>(outC, cln1g, cln1b, tmpA, ctop, s);
        gemm_mma<<<g8, 256, GEMM_SMEM>>>(tmpA, whi + OFF_CATTN, wlo + OFF_CATTN, cattb, outC,
                                         1024, 1024, 1, ctop, s, tec, nullptr, nullptr, outC, 0);
        ln_kernel<<<MM, 256>>>(outC, cln2g, cln2b, tmpA, ctop, s);
        gemm_mma<<<g16, 256, GEMM_SMEM>>>(tmpA, whi + OFF_CFF1, wlo + OFF_CFF1, cff1b, tmpB,
                                          2048, 1024, 2, ctop, s, nullptr, nullptr, nullptr, nullptr, 0);
        gemm_mma<<<g8, 256, GEMM_SMEM>>>(tmpB, whi + OFF_CFF2, wlo + OFF_CFF2, cff2b, outC,
                                         1024, 2048, 4, ctop, s, nullptr, gc, bmean, outC, 0);
        // brainstem
        ln_kernel<<<MM, 256>>>(outB, bln1g, bln1b, tmpA, btop, s);
        gemm_mma<<<g8, 256, GEMM_SMEM>>>(tmpA, whi + OFF_BATTN, wlo + OFF_BATTN, battb, outB,
                                         1024, 1024, 1, btop, s, teb, nullptr, nullptr, outB, 0);
        ln_kernel<<<MM, 256>>>(outB, bln2g, bln2b, tmpA, btop, s);
        gemm_mma<<<g8, 256, GEMM_SMEM>>>(tmpA, whi + OFF_BFF1, wlo + OFF_BFF1, bff1b, tmpB,
                                         1024, 1024, 3, btop, s, nullptr, nullptr, nullptr, nullptr, 0);
        gemm_mma<<<g8, 256, GEMM_SMEM>>>(tmpB, whi + OFF_BFF2, wlo + OFF_BFF2, bff2b, outB,
                                         1024, 1024, 4, btop, s, nullptr, gb, cmean, outB, 0);
    }

    // cross projection (two K=1024 halves, accumulate)
    gemm_mma<<<g8, 256, GEMM_SMEM>>>(outC, whi + OFF_CROSS, wlo + OFF_CROSS, nullptr, outF,
                                    1024, 1024, 0, nullptr, 0, nullptr, nullptr, nullptr, nullptr, 0);
    gemm_mma<<<g8, 256, GEMM_SMEM>>>(outB, whi + OFF_CROSS + 1048576, wlo + OFF_CROSS + 1048576, crossb, outF,
                                    1024, 1024, 0, nullptr, 0, nullptr, nullptr, nullptr, nullptr, 1);
}

// round 10
// speedup vs baseline: 1.8688x; 1.1514x over previous
#include <cuda_runtime.h>
#include <cuda_bf16.h>
#include <math.h>
#include <stdint.h>

// Problem constants
#define BB    8
#define SS    512
#define DD    1024
#define NBLK  8
#define KSEL  4
#define MM    (BB*SS)          // 4096
#define BSD   (BB*SS*DD)       // 4,194,304

// GEMM: CTA 128x128, K-chunk 64, 8 warps (2Mx4N), 3-stage cp.async pipeline
#define STAGE 65536            // Ahi16K + Alo16K + Bhi16K + Blo16K
#define GEMM_SMEM (3*STAGE)    // 196608

// Weight regions (elements) in transposed split-bf16 buffers
#define OFF_CATTN 0ull
#define OFF_CFF1  8388608ull
#define OFF_CFF2  25165824ull
#define OFF_BATTN 41943040ull
#define OFF_BFF1  50331648ull
#define OFF_BFF2  58720256ull
#define OFF_CROSS 67108864ull
#define WTOT      69206016ull

// ---------------- scratch (no cudaMalloc allowed) ----------------
__device__ float g_cmean[BB*DD];
__device__ float g_bmean[BB*DD];
__device__ float g_gate_c[NBLK*DD];
__device__ float g_te_c[NBLK*DD];
__device__ float g_gate_b[NBLK*DD];
__device__ float g_te_b[NBLK*DD];
__device__ int   g_ctop[KSEL];
__device__ int   g_btop[KSEL];
__device__ __nv_bfloat16 g_whi[WTOT];      // transposed weights [N,K] hi
__device__ __nv_bfloat16 g_wlo[WTOT];      // lo
__device__ __nv_bfloat16 g_lnhi[2*BSD];    // LN outputs: c @0, b @BSD
__device__ __nv_bfloat16 g_lnlo[2*BSD];
__device__ __nv_bfloat16 g_ffhi[2*BSD];    // c-ff1 output (M x 2048)
__device__ __nv_bfloat16 g_fflo[2*BSD];
__device__ __nv_bfloat16 g_fbhi[BSD];      // b-ff1 output (M x 1024)
__device__ __nv_bfloat16 g_fblo[BSD];
__device__ __nv_bfloat16 g_xhi[2*BSD];     // cross inputs: c @0, b @BSD
__device__ __nv_bfloat16 g_xlo[2*BSD];

// ---------------- helpers ----------------
__device__ __forceinline__ uint32_t smem_u32(const void* p) {
    uint32_t a;
    asm("{ .reg .u64 t; cvta.to.shared.u64 t, %1; cvt.u32.u64 %0, t; }" : "=r"(a) : "l"(p));
    return a;
}
__device__ __forceinline__ void cp16(uint32_t saddr, const void* g) {
    asm volatile("cp.async.cg.shared.global [%0], [%1], 16;" :: "r"(saddr), "l"(g));
}
__device__ __forceinline__ void cp_commit() { asm volatile("cp.async.commit_group;" ::: "memory"); }
__device__ __forceinline__ void cp_wait0()  { asm volatile("cp.async.wait_group 0;" ::: "memory"); }
__device__ __forceinline__ void cp_wait1()  { asm volatile("cp.async.wait_group 1;" ::: "memory"); }

__device__ __forceinline__ void ldm_x4(uint32_t* r, uint32_t addr) {
    asm volatile("ldmatrix.sync.aligned.m8n8.x4.shared.b16 {%0,%1,%2,%3}, [%4];"
        : "=r"(r[0]), "=r"(r[1]), "=r"(r[2]), "=r"(r[3]) : "r"(addr));
}
__device__ __forceinline__ void mma_bf16(float* c, const uint32_t* a, uint32_t b0, uint32_t b1) {
    asm volatile("mma.sync.aligned.m16n8k16.row.col.f32.bf16.bf16.f32 "
        "{%0,%1,%2,%3}, {%4,%5,%6,%7}, {%8,%9}, {%0,%1,%2,%3};"
        : "+f"(c[0]), "+f"(c[1]), "+f"(c[2]), "+f"(c[3])
        : "r"(a[0]), "r"(a[1]), "r"(a[2]), "r"(a[3]), "r"(b0), "r"(b1));
}
__device__ __forceinline__ uint32_t pack_hi(float a, float b, uint32_t& lo_out) {
    __nv_bfloat16 ha = __float2bfloat16(a);
    __nv_bfloat16 hb = __float2bfloat16(b);
    float la = a - __bfloat162float(ha);
    float lb = b - __bfloat162float(hb);
    __nv_bfloat162 h; h.x = ha; h.y = hb;
    __nv_bfloat162 l; l.x = __float2bfloat16(la); l.y = __float2bfloat16(lb);
    lo_out = *(uint32_t*)&l;
    return *(uint32_t*)&h;
}

// ---------------- job structs ----------------
struct GJob {
    const __nv_bfloat16 *Ahi, *Alo, *A2hi, *A2lo;  // A2: second K half (cross)
    const __nv_bfloat16 *Whi, *Wlo;
    const float *bias;
    float *C;                          // fp32 out (modes 0,1,4)
    __nv_bfloat16 *Chi, *Clo;          // split out (modes 2,3; optional mode 4)
    const float *te, *gate, *sig, *resid;
    const int* top;
    int step, N, Kd, mode, gxo, strideA, kswitch;
};
struct LJob {
    const float *x, *g, *b;
    __nv_bfloat16 *yhi, *ylo;
    const int* top;
    int step;
};

// ---------------- mean over seq dim ----------------
__global__ void mean_kernel(const float* __restrict__ x, float* __restrict__ out) {
    int idx = blockIdx.x * blockDim.x + threadIdx.x;
    if (idx >= BB * DD) return;
    int b = idx / DD, d = idx - b * DD;
    const float* p = x + (size_t)b * SS * DD + d;
    float s = 0.f;
#pragma unroll 8
    for (int i = 0; i < SS; ++i) s += p[(size_t)i * DD];
    out[idx] = s * (1.f / SS);
}

// ---------------- gate/te precompute ----------------
__global__ void prep_kernel(const float* __restrict__ c_tg, const float* __restrict__ b_tg,
                            const float* __restrict__ tor) {
    int i = blockIdx.x * blockDim.x + threadIdx.x;
    if (i >= NBLK * DD) return;
    float t = tor[i & (DD - 1)];
    float gc = 1.f / (1.f + expf(-c_tg[i]));
    g_gate_c[i] = gc; g_te_c[i] = gc * t;
    float gb = 1.f / (1.f + expf(-b_tg[i]));
    g_gate_b[i] = gb; g_te_b[i] = gb * t;
}

// ---------------- routing ----------------
__global__ void routing_kernel(const float* __restrict__ csw, const float* __restrict__ csb,
                               const float* __restrict__ bsw, const float* __restrict__ bsb) {
    __shared__ float red[256];
    __shared__ float score[NBLK];
    int tid = threadIdx.x;
    for (int p = 0; p < 2; ++p) {
        const float* mean = p ? g_bmean : g_cmean;
        const float* sw   = p ? bsw : csw;
        const float* sb   = p ? bsb : csb;
        int* top          = p ? g_btop : g_ctop;
        float a[NBLK];
#pragma unroll
        for (int j = 0; j < NBLK; ++j) a[j] = 0.f;
        for (int d = tid; d < DD; d += 256) {
            float m = mean[d];
#pragma unroll
            for (int j = 0; j < NBLK; ++j) a[j] += m * sw[d * NBLK + j];
        }
        for (int j = 0; j < NBLK; ++j) {
            red[tid] = a[j];
            __syncthreads();
            for (int o = 128; o > 0; o >>= 1) {
                if (tid < o) red[tid] += red[tid + o];
                __syncthreads();
            }
            if (tid == 0) score[j] = red[0] + sb[j];
            __syncthreads();
        }
        if (tid == 0) {
            float adj[NBLK]; bool used[NBLK];
            for (int j = 0; j < NBLK; ++j) {
                adj[j] = (1.f / (1.f + expf(-score[j]))) * 0.6f + 0.2f;
                used[j] = false;
            }
            for (int k = 0; k < KSEL; ++k) {
                int best = 0; float bv = -1e30f;
                for (int j = 0; j < NBLK; ++j)
                    if (!used[j] && adj[j] > bv) { bv = adj[j]; best = j; }
                used[best] = true;
                top[k] = best;
            }
        }
        __syncthreads();
    }
}

// ---------------- fused LayerNorm (two jobs), writes split bf16 ----------------
__global__ void ln2_kernel(LJob j0, LJob j1) {
    const bool first = blockIdx.x < MM;
    LJob j = first ? j0 : j1;
    int row = first ? blockIdx.x : blockIdx.x - MM;
    int tid = threadIdx.x;
    int blk = j.top[j.step];
    float4 v = ((const float4*)(j.x + (size_t)row * DD))[tid];
    float s = v.x + v.y + v.z + v.w;
    float q = v.x * v.x + v.y * v.y + v.z * v.z + v.w * v.w;
#pragma unroll
    for (int o = 16; o > 0; o >>= 1) {
        s += __shfl_down_sync(0xffffffffu, s, o);
        q += __shfl_down_sync(0xffffffffu, q, o);
    }
    __shared__ float ssum[8], sq[8];
    __shared__ float s_mu, s_r;
    int w = tid >> 5, l = tid & 31;
    if (l == 0) { ssum[w] = s; sq[w] = q; }
    __syncthreads();
    if (tid == 0) {
        float S = 0.f, Q = 0.f;
#pragma unroll
        for (int i = 0; i < 8; ++i) { S += ssum[i]; Q += sq[i]; }
        float mu = S * (1.f / DD);
        float var = Q * (1.f / DD) - mu * mu;
        s_mu = mu; s_r = rsqrtf(var + 1e-5f);
    }
    __syncthreads();
    float mu = s_mu, r = s_r;
    float4 gg = ((const float4*)(j.g + (size_t)blk * DD))[tid];
    float4 bb = ((const float4*)(j.b + (size_t)blk * DD))[tid];
    float o0 = (v.x - mu) * r * gg.x + bb.x;
    float o1 = (v.y - mu) * r * gg.y + bb.y;
    float o2 = (v.z - mu) * r * gg.z + bb.z;
    float o3 = (v.w - mu) * r * gg.w + bb.w;
    uint32_t lo0, lo1;
    uint32_t h0 = pack_hi(o0, o1, lo0);
    uint32_t h1 = pack_hi(o2, o3, lo1);
    ((uint2*)j.yhi)[(size_t)row * 256 + tid] = make_uint2(h0, h1);
    ((uint2*)j.ylo)[(size_t)row * 256 + tid] = make_uint2(lo0, lo1);
}

// ---------------- transpose + split-bf16 convert: W[K,N] -> Wt[N,K] hi/lo ----------------
__global__ void transpose_kernel(const float* __restrict__ src,
                                 __nv_bfloat16* __restrict__ dsthi,
                                 __nv_bfloat16* __restrict__ dstlo,
                                 int Kd, int N) {
    __shared__ float ts[32][33];
    int z = blockIdx.z;
    src   += (size_t)z * Kd * N;
    dsthi += (size_t)z * Kd * N;
    dstlo += (size_t)z * Kd * N;
    int n0 = blockIdx.x * 32, k0 = blockIdx.y * 32;
    int t = threadIdx.x;
    {
        int kk = t >> 3, nn4 = (t & 7) * 4;
        float4 v = *(const float4*)(src + (size_t)(k0 + kk) * N + n0 + nn4);
        ts[kk][nn4 + 0] = v.x; ts[kk][nn4 + 1] = v.y;
        ts[kk][nn4 + 2] = v.z; ts[kk][nn4 + 3] = v.w;
    }
    __syncthreads();
    {
        int nn = t >> 3, kk4 = (t & 7) * 4;
        uint32_t h0, h1, l0, l1;
        h0 = pack_hi(ts[kk4 + 0][nn], ts[kk4 + 1][nn], l0);
        h1 = pack_hi(ts[kk4 + 2][nn], ts[kk4 + 3][nn], l1);
        size_t o = (size_t)(n0 + nn) * Kd + k0 + kk4;
        *(uint2*)(dsthi + o) = make_uint2(h0, h1);
        *(uint2*)(dstlo + o) = make_uint2(l0, l1);
    }
}

// ---------------- split-bf16 GEMM (ldmatrix + mma.sync), 3-stage cp.async ----------------
__global__ __launch_bounds__(256, 1)
void gemm_mma(GJob j0, GJob j1, int split) {
    extern __shared__ __align__(1024) char smem[];
    const uint32_t sb32 = smem_u32(smem);
    const GJob j = (blockIdx.x < split) ? j0 : j1;
    const int tid = threadIdx.x, lane = tid & 31, wid = tid >> 5;
    const int bm = blockIdx.y * 128;
    const int bn = (blockIdx.x - j.gxo) * 128;
    const int wm = (wid & 1) * 64, wn = (wid >> 1) * 32;
    const int blk = j.top ? j.top[j.step] : 0;
    const int N = j.N, Kd = j.Kd;
    const __nv_bfloat16* Whi = j.Whi + (size_t)blk * N * Kd;
    const __nv_bfloat16* Wlo = j.Wlo + (size_t)blk * N * Kd;
    const float* bias = j.bias ? (j.bias + (size_t)blk * N) : nullptr;
    const float* te   = j.te   ? (j.te   + (size_t)blk * DD) : nullptr;
    const float* gate = j.gate ? (j.gate + (size_t)blk * DD) : nullptr;

    // loader mapping: 2 threads per row, each covers half the 64-wide K-chunk
    const int lr = tid >> 1, lh = tid & 1;
    const __nv_bfloat16* ahp = j.Ahi + (size_t)(bm + lr) * j.strideA;
    const __nv_bfloat16* alp = j.Alo + (size_t)(bm + lr) * j.strideA;
    const __nv_bfloat16* a2hp = j.A2hi ? j.A2hi + (size_t)(bm + lr) * j.strideA : nullptr;
    const __nv_bfloat16* a2lp = j.A2lo ? j.A2lo + (size_t)(bm + lr) * j.strideA : nullptr;
    const __nv_bfloat16* bhp = Whi + (size_t)(bn + lr) * Kd;
    const __nv_bfloat16* blp = Wlo + (size_t)(bn + lr) * Kd;
    uint32_t c_off[4];
#pragma unroll
    for (int i = 0; i < 4; ++i) {
        int ch = lh * 4 + i;
        c_off[i] = (uint32_t)(lr * 128 + ((ch ^ (lr & 7)) << 4));
    }
    const int nt = Kd >> 6;
    const int ksw = j.kswitch;

    auto issue = [&](int u) {
        int tt = u;
        const __nv_bfloat16 *ah = ahp, *al = alp;
        if (u >= ksw) { tt = u - ksw; ah = a2hp; al = a2lp; }
        uint32_t st = sb32 + (uint32_t)(u % 3) * STAGE;
        const int koA = tt * 64, koB = u * 64;
#pragma unroll
        for (int i = 0; i < 4; ++i) {
            int ce = (lh * 4 + i) * 8;
            cp16(st +         c_off[i], ah  + koA + ce);
            cp16(st + 16384 + c_off[i], al  + koA + ce);
            cp16(st + 32768 + c_off[i], bhp + koB + ce);
            cp16(st + 49152 + c_off[i], blp + koB + ce);
        }
        cp_commit();
    };

    float acc[4][4][4];
#pragma unroll
    for (int mi = 0; mi < 4; ++mi)
#pragma unroll
        for (int ni = 0; ni < 4; ++ni)
#pragma unroll
            for (int q = 0; q < 4; ++q) acc[mi][ni][q] = 0.f;

    issue(0);
    issue(1);

    for (int u = 0; u < nt; ++u) {
        if (u == nt - 1) cp_wait0(); else cp_wait1();
        __syncthreads();                   // chunk u ready; all warps done with u-1
        if (u + 2 < nt) issue(u + 2);      // overwrites stage of u-1 (safe after sync)
        const uint32_t buf = sb32 + (uint32_t)(u % 3) * STAGE;
#pragma unroll
        for (int kk = 0; kk < 4; ++kk) {
            uint32_t ah[4][4], al[4][4], bh[2][4], bl[2][4];
#pragma unroll
            for (int mi = 0; mi < 4; ++mi) {
                int row = wm + mi * 16 + (lane & 15);
                int ch  = kk * 2 + (lane >> 4);
                uint32_t ad = buf + (uint32_t)(row * 128 + ((ch ^ (row & 7)) << 4));
                ldm_x4(ah[mi], ad);
                ldm_x4(al[mi], ad + 16384);
            }
#pragma unroll
            for (int pr = 0; pr < 2; ++pr) {
                int mat = lane >> 3;
                int nrow = wn + pr * 16 + (mat >> 1) * 8 + (lane & 7);
                int ch = kk * 2 + (mat & 1);
                uint32_t bd = buf + 32768 + (uint32_t)(nrow * 128 + ((ch ^ (nrow & 7)) << 4));
                ldm_x4(bh[pr], bd);
                ldm_x4(bl[pr], bd + 16384);
            }
#pragma unroll
            for (int mi = 0; mi < 4; ++mi)
#pragma unroll
                for (int ni = 0; ni < 4; ++ni) {
                    int pr = ni >> 1, o = (ni & 1) * 2;
                    mma_bf16(acc[mi][ni], ah[mi], bh[pr][o], bh[pr][o + 1]);
                    mma_bf16(acc[mi][ni], ah[mi], bl[pr][o], bl[pr][o + 1]);
                    mma_bf16(acc[mi][ni], al[mi], bh[pr][o], bh[pr][o + 1]);
                }
        }
    }

    // ---- epilogue ----
    const int g = lane >> 2, tg = lane & 3;
#pragma unroll
    for (int mi = 0; mi < 4; ++mi) {
#pragma unroll
        for (int ni = 0; ni < 4; ++ni) {
            int c = bn + wn + ni * 8 + tg * 2;
#pragma unroll
            for (int h = 0; h < 2; ++h) {
                int r = bm + wm + mi * 16 + g + h * 8;
                size_t off = (size_t)r * N;
                float x0 = acc[mi][ni][h * 2], x1 = acc[mi][ni][h * 2 + 1];
                if (bias) { x0 += bias[c]; x1 += bias[c + 1]; }
                if (j.mode == 2) {
                    x0 = 0.5f * x0 * (1.f + erff(x0 * 0.70710678118654752f));
                    x1 = 0.5f * x1 * (1.f + erff(x1 * 0.70710678118654752f));
                    uint32_t lo, hi = pack_hi(x0, x1, lo);
                    *(uint32_t*)&j.Chi[off + c] = hi;
                    *(uint32_t*)&j.Clo[off + c] = lo;
                } else if (j.mode == 3) {
                    x0 = tanhf(x0); x1 = tanhf(x1);
                    uint32_t lo, hi = pack_hi(x0, x1, lo);
                    *(uint32_t*)&j.Chi[off + c] = hi;
                    *(uint32_t*)&j.Clo[off + c] = lo;
                } else {
                    if (j.mode == 1) {
                        x0 *= (1.f + te[c]);     x1 *= (1.f + te[c + 1]);
                        x0 = j.resid[off + c] + 0.5f * x0;
                        x1 = j.resid[off + c + 1] + 0.5f * x1;
                    } else if (j.mode == 4) {
                        int bidx = r >> 9;
                        x0 += j.sig[(size_t)bidx * DD + c]     * 0.3f * gate[c];
                        x1 += j.sig[(size_t)bidx * DD + c + 1] * 0.3f * gate[c + 1];
                        x0 = j.resid[off + c] + 0.5f * x0;
                        x1 = j.resid[off + c + 1] + 0.5f * x1;
                    }
                    *(float2*)&j.C[off + c] = make_float2(x0, x1);
                    if (j.mode == 4 && j.Chi) {
                        uint32_t lo, hi = pack_hi(x0, x1, lo);
                        *(uint32_t*)&j.Chi[off + c] = hi;
                        *(uint32_t*)&j.Clo[off + c] = lo;
                    }
                }
            }
        }
    }
}

// ---------------- host orchestration ----------------
extern "C" void kernel_launch(void* const* d_in, const int* in_sizes, int n_in,
                              void* d_out, int out_size) {
    const float* ci     = (const float*)d_in[0];
    const float* bi     = (const float*)d_in[1];
    const float* tor    = (const float*)d_in[2];
    const float* cln1g  = (const float*)d_in[3];
    const float* cln1b  = (const float*)d_in[4];
    const float* cattw  = (const float*)d_in[5];
    const float* cattb  = (const float*)d_in[6];
    const float* cln2g  = (const float*)d_in[7];
    const float* cln2b  = (const float*)d_in[8];
    const float* cff1w  = (const float*)d_in[9];
    const float* cff1b  = (const float*)d_in[10];
    const float* cff2w  = (const float*)d_in[11];
    const float* cff2b  = (const float*)d_in[12];
    const float* ctg    = (const float*)d_in[13];
    const float* bln1g  = (const float*)d_in[14];
    const float* bln1b  = (const float*)d_in[15];
    const float* battw  = (const float*)d_in[16];
    const float* battb  = (const float*)d_in[17];
    const float* bln2g  = (const float*)d_in[18];
    const float* bln2b  = (const float*)d_in[19];
    const float* bff1w  = (const float*)d_in[20];
    const float* bff1b  = (const float*)d_in[21];
    const float* bff2w  = (const float*)d_in[22];
    const float* bff2b  = (const float*)d_in[23];
    const float* btg    = (const float*)d_in[24];
    const float* cselw  = (const float*)d_in[25];
    const float* cselb  = (const float*)d_in[26];
    const float* bselw  = (const float*)d_in[27];
    const float* bselb  = (const float*)d_in[28];
    const float* crossw = (const float*)d_in[29];
    const float* crossb = (const float*)d_in[30];

    float* outC = (float*)d_out;
    float* outB = outC + (size_t)BSD;
    float* outF = outC + (size_t)2 * BSD;

    __nv_bfloat16 *whi, *wlo, *lnhi, *lnlo, *ffhi, *fflo, *fbhi, *fblo, *xhi, *xlo;
    int *ctop, *btop;
    float *cmean, *bmean, *gc, *tec, *gb, *teb;
    cudaGetSymbolAddress((void**)&whi,  g_whi);
    cudaGetSymbolAddress((void**)&wlo,  g_wlo);
    cudaGetSymbolAddress((void**)&lnhi, g_lnhi);
    cudaGetSymbolAddress((void**)&lnlo, g_lnlo);
    cudaGetSymbolAddress((void**)&ffhi, g_ffhi);
    cudaGetSymbolAddress((void**)&fflo, g_fflo);
    cudaGetSymbolAddress((void**)&fbhi, g_fbhi);
    cudaGetSymbolAddress((void**)&fblo, g_fblo);
    cudaGetSymbolAddress((void**)&xhi,  g_xhi);
    cudaGetSymbolAddress((void**)&xlo,  g_xlo);
    cudaGetSymbolAddress((void**)&ctop, g_ctop);
    cudaGetSymbolAddress((void**)&btop, g_btop);
    cudaGetSymbolAddress((void**)&cmean, g_cmean);
    cudaGetSymbolAddress((void**)&bmean, g_bmean);
    cudaGetSymbolAddress((void**)&gc,  g_gate_c);
    cudaGetSymbolAddress((void**)&tec, g_te_c);
    cudaGetSymbolAddress((void**)&gb,  g_gate_b);
    cudaGetSymbolAddress((void**)&teb, g_te_b);

    cudaFuncSetAttribute(gemm_mma, cudaFuncAttributeMaxDynamicSharedMemorySize, GEMM_SMEM);

    mean_kernel<<<(BB * DD + 255) / 256, 256>>>(ci, cmean);
    mean_kernel<<<(BB * DD + 255) / 256, 256>>>(bi, bmean);
    routing_kernel<<<1, 256>>>(cselw, cselb, bselw, bselb);
    prep_kernel<<<(NBLK * DD + 255) / 256, 256>>>(ctg, btg, tor);

    // weight pre-pass: transpose + split-bf16 convert
    transpose_kernel<<<dim3(32, 32, 8), 256>>>(cattw, whi + OFF_CATTN, wlo + OFF_CATTN, 1024, 1024);
    transpose_kernel<<<dim3(64, 32, 8), 256>>>(cff1w, whi + OFF_CFF1,  wlo + OFF_CFF1,  1024, 2048);
    transpose_kernel<<<dim3(32, 64, 8), 256>>>(cff2w, whi + OFF_CFF2,  wlo + OFF_CFF2,  2048, 1024);
    transpose_kernel<<<dim3(32, 32, 8), 256>>>(battw, whi + OFF_BATTN, wlo + OFF_BATTN, 1024, 1024);
    transpose_kernel<<<dim3(32, 32, 8), 256>>>(bff1w, whi + OFF_BFF1,  wlo + OFF_BFF1,  1024, 1024);
    transpose_kernel<<<dim3(32, 32, 8), 256>>>(bff2w, whi + OFF_BFF2,  wlo + OFF_BFF2,  1024, 1024);
    transpose_kernel<<<dim3(32, 64, 1), 256>>>(crossw, whi + OFF_CROSS, wlo + OFF_CROSS, 2048, 1024);

    auto G = [&](const __nv_bfloat16* Ahi, const __nv_bfloat16* Alo,
                 const __nv_bfloat16* W1, const __nv_bfloat16* W2,
                 const float* bias, float* C, __nv_bfloat16* Chi, __nv_bfloat16* Clo,
                 const float* te, const float* gate, const float* sig, const float* resid,
                 const int* top, int step, int N, int Kd, int mode, int gxo) {
        GJob j;
        j.Ahi = Ahi; j.Alo = Alo; j.A2hi = nullptr; j.A2lo = nullptr;
        j.Whi = W1; j.Wlo = W2; j.bias = bias; j.C = C; j.Chi = Chi; j.Clo = Clo;
        j.te = te; j.gate = gate; j.sig = sig; j.resid = resid;
        j.top = top; j.step = step; j.N = N; j.Kd = Kd; j.mode = mode;
        j.gxo = gxo; j.strideA = Kd; j.kswitch = 1 << 30;
        return j;
    };

    for (int s = 0; s < KSEL; ++s) {
        const float* inC = (s == 0) ? ci : outC;
        const float* inB = (s == 0) ? bi : outB;
        // LN1 (fused)
        {
            LJob a{inC, cln1g, cln1b, lnhi, lnlo, ctop, s};
            LJob b{inB, bln1g, bln1b, lnhi + BSD, lnlo + BSD, btop, s};
            ln2_kernel<<<2 * MM, 256>>>(a, b);
        }
        // attn (fused): mode 1
        {
            GJob a = G(lnhi, lnlo, whi + OFF_CATTN, wlo + OFF_CATTN, cattb, outC, nullptr, nullptr,
                       tec, nullptr, nullptr, inC, ctop, s, 1024, 1024, 1, 0);
            GJob b = G(lnhi + BSD, lnlo + BSD, whi + OFF_BATTN, wlo + OFF_BATTN, battb, outB, nullptr, nullptr,
                       teb, nullptr, nullptr, inB, btop, s, 1024, 1024, 1, 8);
            gemm_mma<<<dim3(16, 32), 256, GEMM_SMEM>>>(a, b, 8);
        }
        // LN2 (fused)
        {
            LJob a{outC, cln2g, cln2b, lnhi, lnlo, ctop, s};
            LJob b{outB, bln2g, bln2b, lnhi + BSD, lnlo + BSD, btop, s};
            ln2_kernel<<<2 * MM, 256>>>(a, b);
        }
        // ff1 (fused): c GELU N=2048, b tanh N=1024
        {
            GJob a = G(lnhi, lnlo, whi + OFF_CFF1, wlo + OFF_CFF1, cff1b, nullptr, ffhi, fflo,
                       nullptr, nullptr, nullptr, nullptr, ctop, s, 2048, 1024, 2, 0);
            GJob b = G(lnhi + BSD, lnlo + BSD, whi + OFF_BFF1, wlo + OFF_BFF1, bff1b, nullptr, fbhi, fblo,
                       nullptr, nullptr, nullptr, nullptr, btop, s, 1024, 1024, 3, 16);
            gemm_mma<<<dim3(24, 32), 256, GEMM_SMEM>>>(a, b, 16);
        }
        // ff2 (fused): mode 4; on last step also emit splits for cross
        {
            bool last = (s == KSEL - 1);
            GJob a = G(ffhi, fflo, whi + OFF_CFF2, wlo + OFF_CFF2, cff2b, outC,
                       last ? xhi : nullptr, last ? xlo : nullptr,
                       nullptr, gc, bmean, outC, ctop, s, 1024, 2048, 4, 0);
            GJob b = G(fbhi, fblo, whi + OFF_BFF2, wlo + OFF_BFF2, bff2b, outB,
                       last ? xhi + BSD : nullptr, last ? xlo + BSD : nullptr,
                       nullptr, gb, cmean, outB, btop, s, 1024, 1024, 4, 8);
            gemm_mma<<<dim3(16, 32), 256, GEMM_SMEM>>>(a, b, 8);
        }
    }

    // cross projection: single K=2048 GEMM, A switches halves at chunk 16
    {
        GJob a = G(xhi, xlo, whi + OFF_CROSS, wlo + OFF_CROSS, crossb, outF, nullptr, nullptr,
                   nullptr, nullptr, nullptr, nullptr, nullptr, 0, 1024, 2048, 0, 0);
        a.A2hi = xhi + BSD; a.A2lo = xlo + BSD;
        a.strideA = 1024; a.kswitch = 16;
        gemm_mma<<<dim3(8, 32), 256, GEMM_SMEM>>>(a, a, 8);
    }
}

// round 12
// speedup vs baseline: 1.8956x; 1.0144x over previous
#include <cuda_runtime.h>
#include <cuda_bf16.h>
#include <math.h>
#include <stdint.h>

// Problem constants
#define BB    8
#define SS    512
#define DD    1024
#define NBLK  8
#define KSEL  4
#define MM    (BB*SS)          // 4096
#define BSD   (BB*SS*DD)       // 4,194,304

// GEMM: CTA 128x128, K-chunk 64, 8 warps (2Mx4N), 3-stage cp.async pipeline
#define STAGE 65536            // Ahi16K + Alo16K + Bhi16K + Blo16K
#define GEMM_SMEM (3*STAGE)    // 196608

// Weight regions (elements) in transposed split-bf16 buffers
#define OFF_CATTN 0ull
#define OFF_CFF1  8388608ull
#define OFF_CFF2  25165824ull
#define OFF_BATTN 41943040ull
#define OFF_BFF1  50331648ull
#define OFF_BFF2  58720256ull
#define OFF_CROSS 67108864ull
#define WTOT      69206016ull

// ---------------- scratch (no cudaMalloc allowed) ----------------
__device__ float g_cmean[BB*DD];
__device__ float g_bmean[BB*DD];
__device__ float g_gate_c[NBLK*DD];
__device__ float g_te_c[NBLK*DD];
__device__ float g_gate_b[NBLK*DD];
__device__ float g_te_b[NBLK*DD];
__device__ int   g_ctop[KSEL];
__device__ int   g_btop[KSEL];
__device__ __nv_bfloat16 g_whi[WTOT];      // transposed weights [N,K] hi
__device__ __nv_bfloat16 g_wlo[WTOT];      // lo
__device__ __nv_bfloat16 g_lnhi[2*BSD];    // LN outputs: c @0, b @BSD
__device__ __nv_bfloat16 g_lnlo[2*BSD];
__device__ __nv_bfloat16 g_ffhi[2*BSD];    // c-ff1 output (M x 2048)
__device__ __nv_bfloat16 g_fflo[2*BSD];
__device__ __nv_bfloat16 g_fbhi[BSD];      // b-ff1 output (M x 1024)
__device__ __nv_bfloat16 g_fblo[BSD];
__device__ __nv_bfloat16 g_xhi[2*BSD];     // cross inputs: c @0, b @BSD
__device__ __nv_bfloat16 g_xlo[2*BSD];

// ---------------- helpers ----------------
__device__ __forceinline__ uint32_t smem_u32(const void* p) {
    uint32_t a;
    asm("{ .reg .u64 t; cvta.to.shared.u64 t, %1; cvt.u32.u64 %0, t; }" : "=r"(a) : "l"(p));
    return a;
}
__device__ __forceinline__ void cp16(uint32_t saddr, const void* g) {
    asm volatile("cp.async.cg.shared.global [%0], [%1], 16;" :: "r"(saddr), "l"(g));
}
__device__ __forceinline__ void cp_commit() { asm volatile("cp.async.commit_group;" ::: "memory"); }
__device__ __forceinline__ void cp_wait0()  { asm volatile("cp.async.wait_group 0;" ::: "memory"); }
__device__ __forceinline__ void cp_wait1()  { asm volatile("cp.async.wait_group 1;" ::: "memory"); }

__device__ __forceinline__ void ldm_x4(uint32_t* r, uint32_t addr) {
    asm volatile("ldmatrix.sync.aligned.m8n8.x4.shared.b16 {%0,%1,%2,%3}, [%4];"
        : "=r"(r[0]), "=r"(r[1]), "=r"(r[2]), "=r"(r[3]) : "r"(addr));
}
__device__ __forceinline__ void mma_bf16(float* c, const uint32_t* a, uint32_t b0, uint32_t b1) {
    asm volatile("mma.sync.aligned.m16n8k16.row.col.f32.bf16.bf16.f32 "
        "{%0,%1,%2,%3}, {%4,%5,%6,%7}, {%8,%9}, {%0,%1,%2,%3};"
        : "+f"(c[0]), "+f"(c[1]), "+f"(c[2]), "+f"(c[3])
        : "r"(a[0]), "r"(a[1]), "r"(a[2]), "r"(a[3]), "r"(b0), "r"(b1));
}
__device__ __forceinline__ uint32_t pack_hi(float a, float b, uint32_t& lo_out) {
    __nv_bfloat16 ha = __float2bfloat16(a);
    __nv_bfloat16 hb = __float2bfloat16(b);
    float la = a - __bfloat162float(ha);
    float lb = b - __bfloat162float(hb);
    __nv_bfloat162 h; h.x = ha; h.y = hb;
    __nv_bfloat162 l; l.x = __float2bfloat16(la); l.y = __float2bfloat16(lb);
    lo_out = *(uint32_t*)&l;
    return *(uint32_t*)&h;
}

// ---------------- job structs ----------------
struct GJob {
    const __nv_bfloat16 *Ahi, *Alo, *A2hi, *A2lo;
    const __nv_bfloat16 *Whi, *Wlo;
    const float *bias;
    float *C;
    __nv_bfloat16 *Chi, *Clo;
    const float *te, *gate, *sig, *resid;
    const int* top;
    int step, N, Kd, mode, gxo, strideA, kswitch;
};
struct LJob {
    const float *x, *g, *b;
    __nv_bfloat16 *yhi, *ylo;
    const int* top;
    int step;
};
struct TRegion {
    const float* src;
    __nv_bfloat16 *dhi, *dlo;
    int Kd, N, gx, gy, blocks;   // gx=N/32, gy=Kd/32, blocks=gx*gy*gz
};
struct TRegs { TRegion r[7]; };

// ---------------- launch 1: mean over seq dim, both inputs ----------------
__global__ void mean_all_kernel(const float* __restrict__ ci, const float* __restrict__ bi) {
    int idx = blockIdx.x * blockDim.x + threadIdx.x;   // 0..2*B*D
    const float* x = (idx < BB * DD) ? ci : bi;
    float* out     = (idx < BB * DD) ? g_cmean : g_bmean;
    int k = (idx < BB * DD) ? idx : idx - BB * DD;
    int b = k / DD, d = k - b * DD;
    const float* p = x + (size_t)b * SS * DD + d;
    float s = 0.f;
#pragma unroll 8
    for (int i = 0; i < SS; ++i) s += p[(size_t)i * DD];
    out[k] = s * (1.f / SS);
}

// ---------------- launch 2: routing (block 0) + gate/te prep (blocks 1..32) ----------------
__global__ void routing_prep_kernel(const float* __restrict__ csw, const float* __restrict__ csb,
                                    const float* __restrict__ bsw, const float* __restrict__ bsb,
                                    const float* __restrict__ c_tg, const float* __restrict__ b_tg,
                                    const float* __restrict__ tor) {
    int tid = threadIdx.x;
    if (blockIdx.x > 0) {
        int i = (blockIdx.x - 1) * 256 + tid;
        if (i < NBLK * DD) {
            float t = tor[i & (DD - 1)];
            float gcv = 1.f / (1.f + expf(-c_tg[i]));
            g_gate_c[i] = gcv; g_te_c[i] = gcv * t;
            float gbv = 1.f / (1.f + expf(-b_tg[i]));
            g_gate_b[i] = gbv; g_te_b[i] = gbv * t;
        }
        return;
    }
    __shared__ float red[256];
    __shared__ float score[NBLK];
    for (int p = 0; p < 2; ++p) {
        const float* mean = p ? g_bmean : g_cmean;
        const float* sw   = p ? bsw : csw;
        const float* sb   = p ? bsb : csb;
        int* top          = p ? g_btop : g_ctop;
        float a[NBLK];
#pragma unroll
        for (int j = 0; j < NBLK; ++j) a[j] = 0.f;
        for (int d = tid; d < DD; d += 256) {
            float m = mean[d];
#pragma unroll
            for (int j = 0; j < NBLK; ++j) a[j] += m * sw[d * NBLK + j];
        }
        for (int j = 0; j < NBLK; ++j) {
            red[tid] = a[j];
            __syncthreads();
            for (int o = 128; o > 0; o >>= 1) {
                if (tid < o) red[tid] += red[tid + o];
                __syncthreads();
            }
            if (tid == 0) score[j] = red[0] + sb[j];
            __syncthreads();
        }
        if (tid == 0) {
            float adj[NBLK]; bool used[NBLK];
            for (int j = 0; j < NBLK; ++j) {
                adj[j] = (1.f / (1.f + expf(-score[j]))) * 0.6f + 0.2f;
                used[j] = false;
            }
            for (int k = 0; k < KSEL; ++k) {
                int best = 0; float bv = -1e30f;
                for (int j = 0; j < NBLK; ++j)
                    if (!used[j] && adj[j] > bv) { bv = adj[j]; best = j; }
                used[best] = true;
                top[k] = best;
            }
        }
        __syncthreads();
    }
}

// ---------------- LN device body (split bf16 out) ----------------
__device__ __forceinline__ void ln_body(const LJob& j, int row, int tid) {
    int blk = j.top[j.step];
    float4 v = ((const float4*)(j.x + (size_t)row * DD))[tid];
    float s = v.x + v.y + v.z + v.w;
    float q = v.x * v.x + v.y * v.y + v.z * v.z + v.w * v.w;
#pragma unroll
    for (int o = 16; o > 0; o >>= 1) {
        s += __shfl_down_sync(0xffffffffu, s, o);
        q += __shfl_down_sync(0xffffffffu, q, o);
    }
    __shared__ float ssum[8], sq[8];
    __shared__ float s_mu, s_r;
    int w = tid >> 5, l = tid & 31;
    if (l == 0) { ssum[w] = s; sq[w] = q; }
    __syncthreads();
    if (tid == 0) {
        float S = 0.f, Q = 0.f;
#pragma unroll
        for (int i = 0; i < 8; ++i) { S += ssum[i]; Q += sq[i]; }
        float mu = S * (1.f / DD);
        float var = Q * (1.f / DD) - mu * mu;
        s_mu = mu; s_r = rsqrtf(var + 1e-5f);
    }
    __syncthreads();
    float mu = s_mu, r = s_r;
    float4 gg = ((const float4*)(j.g + (size_t)blk * DD))[tid];
    float4 bb = ((const float4*)(j.b + (size_t)blk * DD))[tid];
    float o0 = (v.x - mu) * r * gg.x + bb.x;
    float o1 = (v.y - mu) * r * gg.y + bb.y;
    float o2 = (v.z - mu) * r * gg.z + bb.z;
    float o3 = (v.w - mu) * r * gg.w + bb.w;
    uint32_t lo0, lo1;
    uint32_t h0 = pack_hi(o0, o1, lo0);
    uint32_t h1 = pack_hi(o2, o3, lo1);
    ((uint2*)j.yhi)[(size_t)row * 256 + tid] = make_uint2(h0, h1);
    ((uint2*)j.ylo)[(size_t)row * 256 + tid] = make_uint2(lo0, lo1);
}

// ---------------- fused LayerNorm (two jobs) ----------------
__global__ void ln2_kernel(LJob j0, LJob j1) {
    const bool first = blockIdx.x < MM;
    ln_body(first ? j0 : j1, first ? blockIdx.x : blockIdx.x - MM, threadIdx.x);
}

// ---------------- launch 3: fused LN1 (both) + all weight transposes ----------------
__global__ void lntrans_kernel(LJob j0, LJob j1, TRegs regs) {
    int tid = threadIdx.x;
    if (blockIdx.x < 2 * MM) {
        const bool first = blockIdx.x < MM;
        ln_body(first ? j0 : j1, first ? blockIdx.x : blockIdx.x - MM, tid);
        return;
    }
    int idx = blockIdx.x - 2 * MM;
    TRegion R = regs.r[0];
#pragma unroll
    for (int i = 0; i < 7; ++i) {
        if (idx < regs.r[i].blocks) { R = regs.r[i]; break; }
        idx -= regs.r[i].blocks;
    }
    int x = idx % R.gx;
    int rem = idx / R.gx;
    int y = rem % R.gy;
    int z = rem / R.gy;
    const float* src = R.src + (size_t)z * R.Kd * R.N;
    __nv_bfloat16* dhi = R.dhi + (size_t)z * R.Kd * R.N;
    __nv_bfloat16* dlo = R.dlo + (size_t)z * R.Kd * R.N;
    int n0 = x * 32, k0 = y * 32;
    __shared__ float ts[32][33];
    {
        int kk = tid >> 3, nn4 = (tid & 7) * 4;
        float4 v = *(const float4*)(src + (size_t)(k0 + kk) * R.N + n0 + nn4);
        ts[kk][nn4 + 0] = v.x; ts[kk][nn4 + 1] = v.y;
        ts[kk][nn4 + 2] = v.z; ts[kk][nn4 + 3] = v.w;
    }
    __syncthreads();
    {
        int nn = tid >> 3, kk4 = (tid & 7) * 4;
        uint32_t h0, h1, l0, l1;
        h0 = pack_hi(ts[kk4 + 0][nn], ts[kk4 + 1][nn], l0);
        h1 = pack_hi(ts[kk4 + 2][nn], ts[kk4 + 3][nn], l1);
        size_t o = (size_t)(n0 + nn) * R.Kd + k0 + kk4;
        *(uint2*)(dhi + o) = make_uint2(h0, h1);
        *(uint2*)(dlo + o) = make_uint2(l0, l1);
    }
}

// ---------------- split-bf16 GEMM (ldmatrix + mma.sync), 3-stage cp.async ----------------
__global__ __launch_bounds__(256, 1)
void gemm_mma(GJob j0, GJob j1, int split) {
    extern __shared__ __align__(1024) char smem[];
    const uint32_t sb32 = smem_u32(smem);
    const GJob j = (blockIdx.x < split) ? j0 : j1;
    const int tid = threadIdx.x, lane = tid & 31, wid = tid >> 5;
    const int bm = blockIdx.y * 128;
    const int bn = (blockIdx.x - j.gxo) * 128;
    const int wm = (wid & 1) * 64, wn = (wid >> 1) * 32;
    const int blk = j.top ? j.top[j.step] : 0;
    const int N = j.N, Kd = j.Kd;
    const __nv_bfloat16* Whi = j.Whi + (size_t)blk * N * Kd;
    const __nv_bfloat16* Wlo = j.Wlo + (size_t)blk * N * Kd;
    const float* bias = j.bias ? (j.bias + (size_t)blk * N) : nullptr;
    const float* te   = j.te   ? (j.te   + (size_t)blk * DD) : nullptr;
    const float* gate = j.gate ? (j.gate + (size_t)blk * DD) : nullptr;

    const int lr = tid >> 1, lh = tid & 1;
    const __nv_bfloat16* ahp = j.Ahi + (size_t)(bm + lr) * j.strideA;
    const __nv_bfloat16* alp = j.Alo + (size_t)(bm + lr) * j.strideA;
    const __nv_bfloat16* a2hp = j.A2hi ? j.A2hi + (size_t)(bm + lr) * j.strideA : nullptr;
    const __nv_bfloat16* a2lp = j.A2lo ? j.A2lo + (size_t)(bm + lr) * j.strideA : nullptr;
    const __nv_bfloat16* bhp = Whi + (size_t)(bn + lr) * Kd;
    const __nv_bfloat16* blp = Wlo + (size_t)(bn + lr) * Kd;
    uint32_t c_off[4];
#pragma unroll
    for (int i = 0; i < 4; ++i) {
        int ch = lh * 4 + i;
        c_off[i] = (uint32_t)(lr * 128 + ((ch ^ (lr & 7)) << 4));
    }
    const int nt = Kd >> 6;
    const int ksw = j.kswitch;

    auto issue = [&](int u) {
        int tt = u;
        const __nv_bfloat16 *ah = ahp, *al = alp;
        if (u >= ksw) { tt = u - ksw; ah = a2hp; al = a2lp; }
        uint32_t st = sb32 + (uint32_t)(u % 3) * STAGE;
        const int koA = tt * 64, koB = u * 64;
#pragma unroll
        for (int i = 0; i < 4; ++i) {
            int ce = (lh * 4 + i) * 8;
            cp16(st +         c_off[i], ah  + koA + ce);
            cp16(st + 16384 + c_off[i], al  + koA + ce);
            cp16(st + 32768 + c_off[i], bhp + koB + ce);
            cp16(st + 49152 + c_off[i], blp + koB + ce);
        }
        cp_commit();
    };

    float acc[4][4][4];
#pragma unroll
    for (int mi = 0; mi < 4; ++mi)
#pragma unroll
        for (int ni = 0; ni < 4; ++ni)
#pragma unroll
            for (int q = 0; q < 4; ++q) acc[mi][ni][q] = 0.f;

    issue(0);
    issue(1);

    for (int u = 0; u < nt; ++u) {
        if (u == nt - 1) cp_wait0(); else cp_wait1();
        __syncthreads();
        if (u + 2 < nt) issue(u + 2);
        const uint32_t buf = sb32 + (uint32_t)(u % 3) * STAGE;
#pragma unroll
        for (int kk = 0; kk < 4; ++kk) {
            uint32_t ah[4][4], al[4][4], bh[2][4], bl[2][4];
#pragma unroll
            for (int mi = 0; mi < 4; ++mi) {
                int row = wm + mi * 16 + (lane & 15);
                int ch  = kk * 2 + (lane >> 4);
                uint32_t ad = buf + (uint32_t)(row * 128 + ((ch ^ (row & 7)) << 4));
                ldm_x4(ah[mi], ad);
                ldm_x4(al[mi], ad + 16384);
            }
#pragma unroll
            for (int pr = 0; pr < 2; ++pr) {
                int mat = lane >> 3;
                int nrow = wn + pr * 16 + (mat >> 1) * 8 + (lane & 7);
                int ch = kk * 2 + (mat & 1);
                uint32_t bd = buf + 32768 + (uint32_t)(nrow * 128 + ((ch ^ (nrow & 7)) << 4));
                ldm_x4(bh[pr], bd);
                ldm_x4(bl[pr], bd + 16384);
            }
            // pass-ordered MMAs: same-acc reuse distance = 16 instructions
#pragma unroll
            for (int mi = 0; mi < 4; ++mi)
#pragma unroll
                for (int ni = 0; ni < 4; ++ni) {
                    int pr = ni >> 1, o = (ni & 1) * 2;
                    mma_bf16(acc[mi][ni], ah[mi], bh[pr][o], bh[pr][o + 1]);
                }
#pragma unroll
            for (int mi = 0; mi < 4; ++mi)
#pragma unroll
                for (int ni = 0; ni < 4; ++ni) {
                    int pr = ni >> 1, o = (ni & 1) * 2;
                    mma_bf16(acc[mi][ni], ah[mi], bl[pr][o], bl[pr][o + 1]);
                }
#pragma unroll
            for (int mi = 0; mi < 4; ++mi)
#pragma unroll
                for (int ni = 0; ni < 4; ++ni) {
                    int pr = ni >> 1, o = (ni & 1) * 2;
                    mma_bf16(acc[mi][ni], al[mi], bh[pr][o], bh[pr][o + 1]);
                }
        }
    }

    // ---- epilogue ----
    const int g = lane >> 2, tg = lane & 3;
#pragma unroll
    for (int mi = 0; mi < 4; ++mi) {
#pragma unroll
        for (int ni = 0; ni < 4; ++ni) {
            int c = bn + wn + ni * 8 + tg * 2;
#pragma unroll
            for (int h = 0; h < 2; ++h) {
                int r = bm + wm + mi * 16 + g + h * 8;
                size_t off = (size_t)r * N;
                float x0 = acc[mi][ni][h * 2], x1 = acc[mi][ni][h * 2 + 1];
                if (bias) { x0 += bias[c]; x1 += bias[c + 1]; }
                if (j.mode == 2) {
                    x0 = 0.5f * x0 * (1.f + erff(x0 * 0.70710678118654752f));
                    x1 = 0.5f * x1 * (1.f + erff(x1 * 0.70710678118654752f));
                    uint32_t lo, hi = pack_hi(x0, x1, lo);
                    *(uint32_t*)&j.Chi[off + c] = hi;
                    *(uint32_t*)&j.Clo[off + c] = lo;
                } else if (j.mode == 3) {
                    x0 = tanhf(x0); x1 = tanhf(x1);
                    uint32_t lo, hi = pack_hi(x0, x1, lo);
                    *(uint32_t*)&j.Chi[off + c] = hi;
                    *(uint32_t*)&j.Clo[off + c] = lo;
                } else {
                    if (j.mode == 1) {
                        x0 *= (1.f + te[c]);     x1 *= (1.f + te[c + 1]);
                        x0 = j.resid[off + c] + 0.5f * x0;
                        x1 = j.resid[off + c + 1] + 0.5f * x1;
                    } else if (j.mode == 4) {
                        int bidx = r >> 9;
                        x0 += j.sig[(size_t)bidx * DD + c]     * 0.3f * gate[c];
                        x1 += j.sig[(size_t)bidx * DD + c + 1] * 0.3f * gate[c + 1];
                        x0 = j.resid[off + c] + 0.5f * x0;
                        x1 = j.resid[off + c + 1] + 0.5f * x1;
                    }
                    *(float2*)&j.C[off + c] = make_float2(x0, x1);
                    if (j.mode == 4 && j.Chi) {
                        uint32_t lo, hi = pack_hi(x0, x1, lo);
                        *(uint32_t*)&j.Chi[off + c] = hi;
                        *(uint32_t*)&j.Clo[off + c] = lo;
                    }
                }
            }
        }
    }
}

// ---------------- host orchestration ----------------
extern "C" void kernel_launch(void* const* d_in, const int* in_sizes, int n_in,
                              void* d_out, int out_size) {
    const float* ci     = (const float*)d_in[0];
    const float* bi     = (const float*)d_in[1];
    const float* tor    = (const float*)d_in[2];
    const float* cln1g  = (const float*)d_in[3];
    const float* cln1b  = (const float*)d_in[4];
    const float* cattw  = (const float*)d_in[5];
    const float* cattb  = (const float*)d_in[6];
    const float* cln2g  = (const float*)d_in[7];
    const float* cln2b  = (const float*)d_in[8];
    const float* cff1w  = (const float*)d_in[9];
    const float* cff1b  = (const float*)d_in[10];
    const float* cff2w  = (const float*)d_in[11];
    const float* cff2b  = (const float*)d_in[12];
    const float* ctg    = (const float*)d_in[13];
    const float* bln1g  = (const float*)d_in[14];
    const float* bln1b  = (const float*)d_in[15];
    const float* battw  = (const float*)d_in[16];
    const float* battb  = (const float*)d_in[17];
    const float* bln2g  = (const float*)d_in[18];
    const float* bln2b  = (const float*)d_in[19];
    const float* bff1w  = (const float*)d_in[20];
    const float* bff1b  = (const float*)d_in[21];
    const float* bff2w  = (const float*)d_in[22];
    const float* bff2b  = (const float*)d_in[23];
    const float* btg    = (const float*)d_in[24];
    const float* cselw  = (const float*)d_in[25];
    const float* cselb  = (const float*)d_in[26];
    const float* bselw  = (const float*)d_in[27];
    const float* bselb  = (const float*)d_in[28];
    const float* crossw = (const float*)d_in[29];
    const float* crossb = (const float*)d_in[30];

    float* outC = (float*)d_out;
    float* outB = outC + (size_t)BSD;
    float* outF = outC + (size_t)2 * BSD;

    __nv_bfloat16 *whi, *wlo, *lnhi, *lnlo, *ffhi, *fflo, *fbhi, *fblo, *xhi, *xlo;
    int *ctop, *btop;
    float *cmean, *bmean, *gc, *tec, *gb, *teb;
    cudaGetSymbolAddress((void**)&whi,  g_whi);
    cudaGetSymbolAddress((void**)&wlo,  g_wlo);
    cudaGetSymbolAddress((void**)&lnhi, g_lnhi);
    cudaGetSymbolAddress((void**)&lnlo, g_lnlo);
    cudaGetSymbolAddress((void**)&ffhi, g_ffhi);
    cudaGetSymbolAddress((void**)&fflo, g_fflo);
    cudaGetSymbolAddress((void**)&fbhi, g_fbhi);
    cudaGetSymbolAddress((void**)&fblo, g_fblo);
    cudaGetSymbolAddress((void**)&xhi,  g_xhi);
    cudaGetSymbolAddress((void**)&xlo,  g_xlo);
    cudaGetSymbolAddress((void**)&ctop, g_ctop);
    cudaGetSymbolAddress((void**)&btop, g_btop);
    cudaGetSymbolAddress((void**)&cmean, g_cmean);
    cudaGetSymbolAddress((void**)&bmean, g_bmean);
    cudaGetSymbolAddress((void**)&gc,  g_gate_c);
    cudaGetSymbolAddress((void**)&tec, g_te_c);
    cudaGetSymbolAddress((void**)&gb,  g_gate_b);
    cudaGetSymbolAddress((void**)&teb, g_te_b);

    cudaFuncSetAttribute(gemm_mma, cudaFuncAttributeMaxDynamicSharedMemorySize, GEMM_SMEM);

    // launch 1: means
    mean_all_kernel<<<(2 * BB * DD + 255) / 256, 256>>>(ci, bi);
    // launch 2: routing + gate/te prep
    routing_prep_kernel<<<33, 256>>>(cselw, cselb, bselw, bselb, ctg, btg, tor);

    // launch 3: LN1(step 0, both pathways) + all weight transposes
    {
        LJob a{ci, cln1g, cln1b, lnhi, lnlo, ctop, 0};
        LJob b{bi, bln1g, bln1b, lnhi + BSD, lnlo + BSD, btop, 0};
        TRegs R;
        auto T = [&](const float* src, unsigned long long off, int Kd, int N, int gz) {
            TRegion r;
            r.src = src; r.dhi = whi + off; r.dlo = wlo + off;
            r.Kd = Kd; r.N = N; r.gx = N / 32; r.gy = Kd / 32;
            r.blocks = r.gx * r.gy * gz;
            return r;
        };
        R.r[0] = T(cattw,  OFF_CATTN, 1024, 1024, 8);
        R.r[1] = T(cff1w,  OFF_CFF1,  1024, 2048, 8);
        R.r[2] = T(cff2w,  OFF_CFF2,  2048, 1024, 8);
        R.r[3] = T(battw,  OFF_BATTN, 1024, 1024, 8);
        R.r[4] = T(bff1w,  OFF_BFF1,  1024, 1024, 8);
        R.r[5] = T(bff2w,  OFF_BFF2,  1024, 1024, 8);
        R.r[6] = T(crossw, OFF_CROSS, 2048, 1024, 1);
        int tblocks = 0;
        for (int i = 0; i < 7; ++i) tblocks += R.r[i].blocks;
        lntrans_kernel<<<2 * MM + tblocks, 256>>>(a, b, R);
    }

    auto G = [&](const __nv_bfloat16* Ahi, const __nv_bfloat16* Alo,
                 const __nv_bfloat16* W1, const __nv_bfloat16* W2,
                 const float* bias, float* C, __nv_bfloat16* Chi, __nv_bfloat16* Clo,
                 const float* te, const float* gate, const float* sig, const float* resid,
                 const int* top, int step, int N, int Kd, int mode, int gxo) {
        GJob j;
        j.Ahi = Ahi; j.Alo = Alo; j.A2hi = nullptr; j.A2lo = nullptr;
        j.Whi = W1; j.Wlo = W2; j.bias = bias; j.C = C; j.Chi = Chi; j.Clo = Clo;
        j.te = te; j.gate = gate; j.sig = sig; j.resid = resid;
        j.top = top; j.step = step; j.N = N; j.Kd = Kd; j.mode = mode;
        j.gxo = gxo; j.strideA = Kd; j.kswitch = 1 << 30;
        return j;
    };

    for (int s = 0; s < KSEL; ++s) {
        const float* inC = (s == 0) ? ci : outC;
        const float* inB = (s == 0) ? bi : outB;
        // LN1 for s>0 (s==0 done in lntrans_kernel)
        if (s > 0) {
            LJob a{inC, cln1g, cln1b, lnhi, lnlo, ctop, s};
            LJob b{inB, bln1g, bln1b, lnhi + BSD, lnlo + BSD, btop, s};
            ln2_kernel<<<2 * MM, 256>>>(a, b);
        }
        // attn (fused, mode 1) — at s==0 this is kernel launch #4 (profiled)
        {
            GJob a = G(lnhi, lnlo, whi + OFF_CATTN, wlo + OFF_CATTN, cattb, outC, nullptr, nullptr,
                       tec, nullptr, nullptr, inC, ctop, s, 1024, 1024, 1, 0);
            GJob b = G(lnhi + BSD, lnlo + BSD, whi + OFF_BATTN, wlo + OFF_BATTN, battb, outB, nullptr, nullptr,
                       teb, nullptr, nullptr, inB, btop, s, 1024, 1024, 1, 8);
            gemm_mma<<<dim3(16, 32), 256, GEMM_SMEM>>>(a, b, 8);
        }
        // LN2 (fused)
        {
            LJob a{outC, cln2g, cln2b, lnhi, lnlo, ctop, s};
            LJob b{outB, bln2g, bln2b, lnhi + BSD, lnlo + BSD, btop, s};
            ln2_kernel<<<2 * MM, 256>>>(a, b);
        }
        // ff1 (fused): c GELU N=2048, b tanh N=1024
        {
            GJob a = G(lnhi, lnlo, whi + OFF_CFF1, wlo + OFF_CFF1, cff1b, nullptr, ffhi, fflo,
                       nullptr, nullptr, nullptr, nullptr, ctop, s, 2048, 1024, 2, 0);
            GJob b = G(lnhi + BSD, lnlo + BSD, whi + OFF_BFF1, wlo + OFF_BFF1, bff1b, nullptr, fbhi, fblo,
                       nullptr, nullptr, nullptr, nullptr, btop, s, 1024, 1024, 3, 16);
            gemm_mma<<<dim3(24, 32), 256, GEMM_SMEM>>>(a, b, 16);
        }
        // ff2 (fused, mode 4); on last step also emit splits for cross
        {
            bool last = (s == KSEL - 1);
            GJob a = G(ffhi, fflo, whi + OFF_CFF2, wlo + OFF_CFF2, cff2b, outC,
                       last ? xhi : nullptr, last ? xlo : nullptr,
                       nullptr, gc, bmean, outC, ctop, s, 1024, 2048, 4, 0);
            GJob b = G(fbhi, fblo, whi + OFF_BFF2, wlo + OFF_BFF2, bff2b, outB,
                       last ? xhi + BSD : nullptr, last ? xlo + BSD : nullptr,
                       nullptr, gb, cmean, outB, btop, s, 1024, 1024, 4, 8);
            gemm_mma<<<dim3(16, 32), 256, GEMM_SMEM>>>(a, b, 8);
        }
    }

    // cross projection: single K=2048 GEMM, A switches halves at chunk 16
    {
        GJob a = G(xhi, xlo, whi + OFF_CROSS, wlo + OFF_CROSS, crossb, outF, nullptr, nullptr,
                   nullptr, nullptr, nullptr, nullptr, nullptr, 0, 1024, 2048, 0, 0);
        a.A2hi = xhi + BSD; a.A2lo = xlo + BSD;
        a.strideA = 1024; a.kswitch = 16;
        gemm_mma<<<dim3(8, 32), 256, GEMM_SMEM>>>(a, a, 8);
    }
}